// round 1
// baseline (speedup 1.0000x reference)
#include <cuda_runtime.h>

#define DEVINL __device__ __forceinline__

struct cplx { float x, y; };

DEVINL cplx cmul(cplx a, cplx b) {
    cplx r;
    r.x = fmaf(a.x, b.x, -a.y * b.y);
    r.y = fmaf(a.x, b.y,  a.y * b.x);
    return r;
}
// acc + a*b
DEVINL cplx cfma2(cplx a, cplx b, cplx acc) {
    acc.x = fmaf(a.x, b.x, fmaf(-a.y, b.y, acc.x));
    acc.y = fmaf(a.x, b.y, fmaf( a.y, b.x, acc.y));
    return acc;
}

// fused U[layer][qubit] = RZ(w2)*RY(w1)*RX(w0), stored as 8 floats:
// u00.x u00.y u01.x u01.y u10.x u10.y u11.x u11.y
__device__ float g_U[2][8][8];

__global__ void qnn_setup(const float* __restrict__ w) {
    int i = threadIdx.x;
    if (i >= 16) return;
    int l = i >> 3, q = i & 7;
    float a = w[(l * 8 + q) * 3 + 0];
    float b = w[(l * 8 + q) * 3 + 1];
    float c = w[(l * 8 + q) * 3 + 2];
    float sa, ca; sincosf(0.5f * a, &sa, &ca);
    float sb, cb; sincosf(0.5f * b, &sb, &cb);
    float sc, cc; sincosf(0.5f * c, &sc, &cc);
    // M = RY * RX
    cplx m00 = {  cb * ca,  sb * sa };
    cplx m01 = { -sb * ca, -cb * sa };
    cplx m10 = {  sb * ca, -cb * sa };
    cplx m11 = {  cb * ca, -sb * sa };
    cplx e0 = { cc, -sc };   // e^{-ic/2}
    cplx e1 = { cc,  sc };   // e^{+ic/2}
    cplx u00 = cmul(e0, m00), u01 = cmul(e0, m01);
    cplx u10 = cmul(e1, m10), u11 = cmul(e1, m11);
    float* dst = g_U[l][q];
    dst[0] = u00.x; dst[1] = u00.y; dst[2] = u01.x; dst[3] = u01.y;
    dst[4] = u10.x; dst[5] = u10.y; dst[6] = u11.x; dst[7] = u11.y;
}

// Layout: 8 lanes per sample (sample-in-warp g = lane>>3, sub-id t = lane&7).
// Amp index (8 bits, wire w <-> bit 7-w): bits 7,6,5 = t2,t1,t0 (lane bits),
// bits 4..0 = local register index j bits 4..0.
__global__ void __launch_bounds__(256) qnn_main(
    const float* __restrict__ x, float* __restrict__ out, int B)
{
    const unsigned FULL = 0xffffffffu;
    int L = threadIdx.x & 31;
    int warp = blockIdx.x * (blockDim.x >> 5) + (threadIdx.x >> 5);
    int g = L >> 3;
    int t = L & 7;
    long long b = (long long)warp * 4 + g;
    bool valid = (b < (long long)B);

    float xv = valid ? x[b * 8 + t] : 0.0f;
    float s, c;
    sincosf(0.5f * xv, &s, &c);

    // Layer-0 fused with embedding: V_q = U[0][q] * RX(x_q), only column 0 needed.
    // V00 = c*u00 + (-i s)*u01 ; V10 = c*u10 + (-i s)*u11 ; (-i s)*(p,q) = (s*q, -s*p)
    const float* u0 = g_U[0][t];
    cplx myv0, myv1;
    myv0.x = fmaf(c, u0[0],  s * u0[3]);
    myv0.y = fmaf(c, u0[1], -s * u0[2]);
    myv1.x = fmaf(c, u0[4],  s * u0[7]);
    myv1.y = fmaf(c, u0[5], -s * u0[6]);

    // broadcast columns: va[q] = V_q[0], vb[q] = V_q[1]
    cplx va[8], vb[8];
    int base = L & ~7;
#pragma unroll
    for (int q = 0; q < 8; q++) {
        int src = base | q;
        va[q].x = __shfl_sync(FULL, myv0.x, src);
        va[q].y = __shfl_sync(FULL, myv0.y, src);
        vb[q].x = __shfl_sync(FULL, myv1.x, src);
        vb[q].y = __shfl_sync(FULL, myv1.y, src);
    }

    int t2 = (t >> 2) & 1, t1 = (t >> 1) & 1, t0 = t & 1;

    // State after layer-0 rotations + CNOT ring (ring = XOR basis permutation):
    // amp(f) = v2[t1^t0] * v3[t0^j4] * v4[j4^j3] * v5[j3^j2] * v6[j2^j1]
    //          * v7[j1^j0] * v0[t2^j0] * v1[t2^t1^j0]
    cplx Cl   = (t1 ^ t0) ? vb[2] : va[2];
    cplx v3s0 = t0 ? vb[3] : va[3];   // j4 = 0
    cplx v3s1 = t0 ? va[3] : vb[3];   // j4 = 1
    cplx W0 = cmul((t2 ? vb[0] : va[0]), ((t2 ^ t1) ? vb[1] : va[1])); // j0=0
    cplx W1 = cmul((t2 ? va[0] : vb[0]), ((t2 ^ t1) ? va[1] : vb[1])); // j0=1
    cplx G00 = cmul(va[7], W0);   // j1=0, j0=0
    cplx G01 = cmul(vb[7], W1);   // j1=0, j0=1
    cplx G10 = cmul(vb[7], W0);   // j1=1, j0=0
    cplx G11 = cmul(va[7], W1);   // j1=1, j0=1

    cplx amp[32];
    // in-place doubling (descending h so sources aren't clobbered)
    amp[0] = cmul(Cl, v3s0);
    amp[1] = cmul(Cl, v3s1);
    // level j3: factor v4[j4^j3], h = j4
#pragma unroll
    for (int h = 1; h >= 0; h--) {
        cplx src = amp[h];
        amp[2 * h + 1] = cmul(src, ((h & 1) ^ 1) ? vb[4] : va[4]);
        amp[2 * h]     = cmul(src, ((h & 1) ^ 0) ? vb[4] : va[4]);
    }
    // level j2: factor v5[j3^j2]
#pragma unroll
    for (int h = 3; h >= 0; h--) {
        cplx src = amp[h];
        amp[2 * h + 1] = cmul(src, ((h & 1) ^ 1) ? vb[5] : va[5]);
        amp[2 * h]     = cmul(src, ((h & 1) ^ 0) ? vb[5] : va[5]);
    }
    // level j1: factor v6[j2^j1]
#pragma unroll
    for (int h = 7; h >= 0; h--) {
        cplx src = amp[h];
        amp[2 * h + 1] = cmul(src, ((h & 1) ^ 1) ? vb[6] : va[6]);
        amp[2 * h]     = cmul(src, ((h & 1) ^ 0) ? vb[6] : va[6]);
    }
    // level j0: factor G[j1][j0]
#pragma unroll
    for (int h = 15; h >= 0; h--) {
        cplx src = amp[h];
        if (h & 1) {
            amp[2 * h + 1] = cmul(src, G11);
            amp[2 * h]     = cmul(src, G10);
        } else {
            amp[2 * h + 1] = cmul(src, G01);
            amp[2 * h]     = cmul(src, G00);
        }
    }

    // ---- layer-1 fused gates ----
    // lane-crossing wires 0,1,2 (index bits 7,6,5 -> lane xor 4,2,1)
#pragma unroll
    for (int q = 0; q < 3; q++) {
        const float* u = g_U[1][q];
        cplx u00 = { u[0], u[1] }, u01 = { u[2], u[3] };
        cplx u10 = { u[4], u[5] }, u11 = { u[6], u[7] };
        int lb = 2 - q;
        int xm = 1 << lb;
        int mybit = (t >> lb) & 1;
        cplx cA = mybit ? u11 : u00;
        cplx cB = mybit ? u10 : u01;
#pragma unroll
        for (int j = 0; j < 32; j++) {
            cplx pr;
            pr.x = __shfl_xor_sync(FULL, amp[j].x, xm);
            pr.y = __shfl_xor_sync(FULL, amp[j].y, xm);
            amp[j] = cfma2(cB, pr, cmul(cA, amp[j]));
        }
    }
    // local wires 3..7 (index bits 4..0)
#pragma unroll
    for (int q = 3; q < 8; q++) {
        const float* u = g_U[1][q];
        cplx u00 = { u[0], u[1] }, u01 = { u[2], u[3] };
        cplx u10 = { u[4], u[5] }, u11 = { u[6], u[7] };
        int m = 1 << (7 - q);
#pragma unroll
        for (int j = 0; j < 32; j++) {
            if ((j & m) == 0) {
                cplx a0 = amp[j], a1 = amp[j + m];
                amp[j]     = cfma2(u01, a1, cmul(u00, a0));
                amp[j + m] = cfma2(u11, a1, cmul(u10, a0));
            }
        }
    }

    // ---- measurement (final CNOT ring folded into parity masks) ----
    float pr[32];
#pragma unroll
    for (int j = 0; j < 32; j++)
        pr[j] = fmaf(amp[j].x, amp[j].x, amp[j].y * amp[j].y);

    // signed-sum network over local bits j0..j4
    float s1[16], d1[16];
#pragma unroll
    for (int h = 0; h < 16; h++) { s1[h] = pr[2*h] + pr[2*h+1]; d1[h] = pr[2*h] - pr[2*h+1]; }
    float s2[8], a2[8], b2[8];
#pragma unroll
    for (int h = 0; h < 8; h++) {
        s2[h] = s1[2*h] + s1[2*h+1];
        a2[h] = s1[2*h] - s1[2*h+1];
        b2[h] = d1[2*h] - d1[2*h+1];
    }
    float s3[4], c3[4], a3[4], b3[4];
#pragma unroll
    for (int h = 0; h < 4; h++) {
        s3[h] = s2[2*h] + s2[2*h+1];
        c3[h] = s2[2*h] - s2[2*h+1];
        a3[h] = a2[2*h] - a2[2*h+1];
        b3[h] = b2[2*h] - b2[2*h+1];
    }
    float s4[2], e4[2], c4[2], a4[2], b4[2];
#pragma unroll
    for (int h = 0; h < 2; h++) {
        s4[h] = s3[2*h] + s3[2*h+1];
        e4[h] = s3[2*h] - s3[2*h+1];
        c4[h] = c3[2*h] - c3[2*h+1];
        a4[h] = a3[2*h] - a3[2*h+1];
        b4[h] = b3[2*h] - b3[2*h+1];
    }
    float S00 = s4[0] + s4[1];   // mask 0x00
    float S10 = s4[0] - s4[1];   // mask 0x10 (parity j4)
    float S18 = e4[0] - e4[1];   // mask 0x18
    float S1C = c4[0] - c4[1];   // mask 0x1C
    float S1E = a4[0] - a4[1];   // mask 0x1E
    float S1F = b4[0] - b4[1];   // mask 0x1F

    // lane signs from high (lane-bit) parts of the parity masks
    float sg3 = ((__popc(t & 3) & 1) ? -1.0f : 1.0f);
    float sg6 = ((__popc(t & 6) & 1) ? -1.0f : 1.0f);
    float sg7 = ((__popc(t & 7) & 1) ? -1.0f : 1.0f);

    float r[8];
    r[0] = sg3 * S1F;   // Z0 -> wires {1..7}: mask 0x7F
    r[1] = sg6 * S00;   // Z1 -> {0,1}:       mask 0xC0
    r[2] = sg7 * S00;   // Z2 -> {0,1,2}:     mask 0xE0
    r[3] = sg7 * S10;   // 0xF0
    r[4] = sg7 * S18;   // 0xF8
    r[5] = sg7 * S1C;   // 0xFC
    r[6] = sg7 * S1E;   // 0xFE
    r[7] = sg7 * S1F;   // 0xFF

    // butterfly reduce within the 8-lane sample group
#pragma unroll
    for (int d = 1; d < 8; d <<= 1) {
#pragma unroll
        for (int i = 0; i < 8; i++)
            r[i] += __shfl_xor_sync(FULL, r[i], d);
    }

    if (valid) {
#pragma unroll
        for (int k = 0; k < 8; k++)
            if (t == k) out[b * 8 + k] = r[k];
    }
}

extern "C" void kernel_launch(void* const* d_in, const int* in_sizes, int n_in,
                              void* d_out, int out_size)
{
    const float* x = (const float*)d_in[0];
    const float* w = (const float*)d_in[1];
    float* out = (float*)d_out;
    int B = in_sizes[0] / 8;

    qnn_setup<<<1, 32>>>(w);

    int warps = (B + 3) / 4;            // 4 samples per warp
    int blocks = (warps + 7) / 8;       // 8 warps per block
    qnn_main<<<blocks, 256>>>(x, out, B);
}

// round 2
// speedup vs baseline: 1.1481x; 1.1481x over previous
#include <cuda_runtime.h>

#define DEVINL __device__ __forceinline__

typedef unsigned long long u64;

struct cplx { float x, y; };

DEVINL cplx cmul(cplx a, cplx b) {
    cplx r;
    r.x = fmaf(a.x, b.x, -a.y * b.y);
    r.y = fmaf(a.x, b.y,  a.y * b.x);
    return r;
}

// ---- packed f32x2 helpers (sm_103a FFMA2 path) ----
DEVINL u64 pk(float lo, float hi) {
    u64 r; asm("mov.b64 %0,{%1,%2};" : "=l"(r) : "f"(lo), "f"(hi)); return r;
}
DEVINL void upk(u64 a, float& lo, float& hi) {
    asm("mov.b64 {%0,%1},%2;" : "=f"(lo), "=f"(hi) : "l"(a));
}
DEVINL u64 spl(float v) { return pk(v, v); }
DEVINL u64 fma2(u64 a, u64 b, u64 c) {
    u64 r; asm("fma.rn.f32x2 %0,%1,%2,%3;" : "=l"(r) : "l"(a), "l"(b), "l"(c)); return r;
}
DEVINL u64 mul2(u64 a, u64 b) {
    u64 r; asm("mul.rn.f32x2 %0,%1,%2;" : "=l"(r) : "l"(a), "l"(b)); return r;
}
DEVINL u64 swp(u64 a) { float x, y; upk(a, x, y); return pk(y, x); }

// fused U[layer][qubit] = RZ(w2)*RY(w1)*RX(w0), 8 floats:
// u00.x u00.y u01.x u01.y u10.x u10.y u11.x u11.y
__device__ float g_U[2][8][8];

__global__ void qnn_setup(const float* __restrict__ w) {
    int i = threadIdx.x;
    if (i >= 16) return;
    int l = i >> 3, q = i & 7;
    float a = w[(l * 8 + q) * 3 + 0];
    float b = w[(l * 8 + q) * 3 + 1];
    float c = w[(l * 8 + q) * 3 + 2];
    float sa, ca; sincosf(0.5f * a, &sa, &ca);
    float sb, cb; sincosf(0.5f * b, &sb, &cb);
    float sc, cc; sincosf(0.5f * c, &sc, &cc);
    cplx m00 = {  cb * ca,  sb * sa };
    cplx m01 = { -sb * ca, -cb * sa };
    cplx m10 = {  sb * ca, -cb * sa };
    cplx m11 = {  cb * ca, -sb * sa };
    cplx e0 = { cc, -sc };
    cplx e1 = { cc,  sc };
    cplx u00 = cmul(e0, m00), u01 = cmul(e0, m01);
    cplx u10 = cmul(e1, m10), u11 = cmul(e1, m11);
    float* dst = g_U[l][q];
    dst[0] = u00.x; dst[1] = u00.y; dst[2] = u01.x; dst[3] = u01.y;
    dst[4] = u10.x; dst[5] = u10.y; dst[6] = u11.x; dst[7] = u11.y;
}

// Layout: 8 lanes per sample (g = lane>>3 sample-in-warp, t = lane&7).
// Amp index bits [7..0]: bits 7,6,5 = t2,t1,t0 (lane bits); bits 4..1 = k
// (packed-register index); bit 0 = packed f32x2 lane p (wire 7).
__global__ void __launch_bounds__(256) qnn_main(
    const float* __restrict__ x, float* __restrict__ out, int B)
{
    const unsigned FULL = 0xffffffffu;
    int L = threadIdx.x & 31;
    int warp = blockIdx.x * (blockDim.x >> 5) + (threadIdx.x >> 5);
    int g = L >> 3;
    int t = L & 7;
    long long b = (long long)warp * 4 + g;
    bool valid = (b < (long long)B);

    float xv = valid ? x[b * 8 + t] : 0.0f;
    float s, c;
    sincosf(0.5f * xv, &s, &c);

    // Layer-0 fused with embedding: V_q = U[0][q]*RX(x_q), column 0 only.
    const float* u0 = g_U[0][t];
    cplx myv0, myv1;
    myv0.x = fmaf(c, u0[0],  s * u0[3]);
    myv0.y = fmaf(c, u0[1], -s * u0[2]);
    myv1.x = fmaf(c, u0[4],  s * u0[7]);
    myv1.y = fmaf(c, u0[5], -s * u0[6]);

    cplx va[8], vb[8];
    int base = L & ~7;
#pragma unroll
    for (int q = 0; q < 8; q++) {
        int src = base | q;
        va[q].x = __shfl_sync(FULL, myv0.x, src);
        va[q].y = __shfl_sync(FULL, myv0.y, src);
        vb[q].x = __shfl_sync(FULL, myv1.x, src);
        vb[q].y = __shfl_sync(FULL, myv1.y, src);
    }

    int t2 = (t >> 2) & 1, t1 = (t >> 1) & 1, t0 = t & 1;

    // Post layer-0 (rotations + CNOT ring as XOR permutation):
    // amp(f) = v2[t1^t0]*v3[t0^j4]*v4[j4^j3]*v5[j3^j2]*v6[j2^j1]
    //          *v7[j1^j0]*v0[t2^j0]*v1[t2^t1^j0]
    cplx Cl   = (t1 ^ t0) ? vb[2] : va[2];
    cplx v3s0 = t0 ? vb[3] : va[3];
    cplx v3s1 = t0 ? va[3] : vb[3];
    cplx W0 = cmul((t2 ? vb[0] : va[0]), ((t2 ^ t1) ? vb[1] : va[1])); // j0=0
    cplx W1 = cmul((t2 ? va[0] : vb[0]), ((t2 ^ t1) ? va[1] : vb[1])); // j0=1
    cplx G00 = cmul(va[7], W0);   // j1=0, j0=0
    cplx G01 = cmul(vb[7], W1);   // j1=0, j0=1
    cplx G10 = cmul(vb[7], W0);   // j1=1, j0=0
    cplx G11 = cmul(va[7], W1);   // j1=1, j0=1

    // scalar doubling tree to 16 amps over bits [j4 j3 j2 j1]
    cplx amp[16];
    amp[0] = cmul(Cl, v3s0);
    amp[1] = cmul(Cl, v3s1);
#pragma unroll
    for (int h = 1; h >= 0; h--) {               // add j3
        cplx src = amp[h];
        amp[2 * h + 1] = cmul(src, ((h & 1) ^ 1) ? vb[4] : va[4]);
        amp[2 * h]     = cmul(src, ((h & 1) ^ 0) ? vb[4] : va[4]);
    }
#pragma unroll
    for (int h = 3; h >= 0; h--) {               // add j2
        cplx src = amp[h];
        amp[2 * h + 1] = cmul(src, ((h & 1) ^ 1) ? vb[5] : va[5]);
        amp[2 * h]     = cmul(src, ((h & 1) ^ 0) ? vb[5] : va[5]);
    }
#pragma unroll
    for (int h = 7; h >= 0; h--) {               // add j1
        cplx src = amp[h];
        amp[2 * h + 1] = cmul(src, ((h & 1) ^ 1) ? vb[6] : va[6]);
        amp[2 * h]     = cmul(src, ((h & 1) ^ 0) ? vb[6] : va[6]);
    }

    // final level packed over j0: X[k]=(amp.x|p=0, amp.x|p=1), Y likewise
    u64 GX0 = pk(G00.x, G01.x), GY0 = pk(G00.y, G01.y);
    u64 GX1 = pk(G10.x, G11.x), GY1 = pk(G10.y, G11.y);
    u64 nGY0 = pk(-G00.y, -G01.y), nGY1 = pk(-G10.y, -G11.y);
    u64 X[16], Y[16];
#pragma unroll
    for (int h = 0; h < 16; h++) {
        float sx = amp[h].x, sy = amp[h].y;
        u64 sx2 = spl(sx), sy2 = spl(sy);
        u64 gx = (h & 1) ? GX1 : GX0;
        u64 gy = (h & 1) ? GY1 : GY0;
        u64 ngy = (h & 1) ? nGY1 : nGY0;
        X[h] = fma2(sx2, gx, mul2(sy2, ngy));
        Y[h] = fma2(sx2, gy, mul2(sy2, gx));
    }

    // ---- layer-1 gates ----
    // lane-crossing wires 0,1,2 (lane bits t2,t1,t0 -> xor 4,2,1)
#pragma unroll
    for (int q = 0; q < 3; q++) {
        const float* u = g_U[1][q];
        int lb = 2 - q;
        int xm = 1 << lb;
        int mybit = (t >> lb) & 1;
        cplx cA = mybit ? (cplx){u[6], u[7]} : (cplx){u[0], u[1]};
        cplx cB = mybit ? (cplx){u[4], u[5]} : (cplx){u[2], u[3]};
        u64 Ax = spl(cA.x), Ay = spl(cA.y), nAy = spl(-cA.y);
        u64 Bx = spl(cB.x), By = spl(cB.y), nBy = spl(-cB.y);
#pragma unroll
        for (int k = 0; k < 16; k++) {
            u64 Xp = __shfl_xor_sync(FULL, X[k], xm);
            u64 Yp = __shfl_xor_sync(FULL, Y[k], xm);
            u64 nX = fma2(Ax, X[k], fma2(nAy, Y[k], fma2(Bx, Xp, mul2(nBy, Yp))));
            u64 nY = fma2(Ax, Y[k], fma2(Ay, X[k], fma2(Bx, Yp, mul2(By, Xp))));
            X[k] = nX; Y[k] = nY;
        }
    }
    // local wires 3..6 (k bits 3..0)
#pragma unroll
    for (int q = 3; q < 7; q++) {
        const float* u = g_U[1][q];
        u64 u00x = spl(u[0]), u00y = spl(u[1]), n00y = spl(-u[1]);
        u64 u01x = spl(u[2]), u01y = spl(u[3]), n01y = spl(-u[3]);
        u64 u10x = spl(u[4]), u10y = spl(u[5]), n10y = spl(-u[5]);
        u64 u11x = spl(u[6]), u11y = spl(u[7]), n11y = spl(-u[7]);
        int m = 1 << (6 - q);
#pragma unroll
        for (int k = 0; k < 16; k++) {
            if ((k & m) == 0) {
                u64 X0 = X[k], Y0 = Y[k], X1 = X[k + m], Y1 = Y[k + m];
                X[k]     = fma2(u00x, X0, fma2(n00y, Y0, fma2(u01x, X1, mul2(n01y, Y1))));
                Y[k]     = fma2(u00x, Y0, fma2(u00y, X0, fma2(u01x, Y1, mul2(u01y, X1))));
                X[k + m] = fma2(u10x, X0, fma2(n10y, Y0, fma2(u11x, X1, mul2(n11y, Y1))));
                Y[k + m] = fma2(u10x, Y0, fma2(u10y, X0, fma2(u11x, Y1, mul2(u11y, X1))));
            }
        }
    }
    // wire 7 = packed dimension p
    {
        const float* u = g_U[1][7];
        u64 CAx = pk(u[0], u[6]), CAy = pk(u[1], u[7]), nCAy = pk(-u[1], -u[7]);
        u64 CBx = pk(u[2], u[4]), CBy = pk(u[3], u[5]), nCBy = pk(-u[3], -u[5]);
#pragma unroll
        for (int k = 0; k < 16; k++) {
            u64 X0 = X[k], Y0 = Y[k];
            u64 Xs = swp(X0), Ys = swp(Y0);
            X[k] = fma2(CAx, X0, fma2(nCAy, Y0, fma2(CBx, Xs, mul2(nCBy, Ys))));
            Y[k] = fma2(CAx, Y0, fma2(CAy, X0, fma2(CBx, Ys, mul2(CBy, Xs))));
        }
    }

    // ---- measurement (final CNOT ring folded into parity masks) ----
    float s1[16], d1[16];
#pragma unroll
    for (int k = 0; k < 16; k++) {
        u64 PR = fma2(X[k], X[k], mul2(Y[k], Y[k]));
        float plo, phi; upk(PR, plo, phi);
        s1[k] = plo + phi;
        d1[k] = plo - phi;
    }
    float s2[8], a2[8], b2[8];
#pragma unroll
    for (int h = 0; h < 8; h++) {
        s2[h] = s1[2*h] + s1[2*h+1];
        a2[h] = s1[2*h] - s1[2*h+1];
        b2[h] = d1[2*h] - d1[2*h+1];
    }
    float s3[4], c3[4], a3[4], b3[4];
#pragma unroll
    for (int h = 0; h < 4; h++) {
        s3[h] = s2[2*h] + s2[2*h+1];
        c3[h] = s2[2*h] - s2[2*h+1];
        a3[h] = a2[2*h] - a2[2*h+1];
        b3[h] = b2[2*h] - b2[2*h+1];
    }
    float s4[2], e4[2], c4[2], a4[2], b4[2];
#pragma unroll
    for (int h = 0; h < 2; h++) {
        s4[h] = s3[2*h] + s3[2*h+1];
        e4[h] = s3[2*h] - s3[2*h+1];
        c4[h] = c3[2*h] - c3[2*h+1];
        a4[h] = a3[2*h] - a3[2*h+1];
        b4[h] = b3[2*h] - b3[2*h+1];
    }
    float S00 = s4[0] + s4[1];
    float S10 = s4[0] - s4[1];
    float S18 = e4[0] - e4[1];
    float S1C = c4[0] - c4[1];
    float S1E = a4[0] - a4[1];
    float S1F = b4[0] - b4[1];

    float sg3 = ((__popc(t & 3) & 1) ? -1.0f : 1.0f);
    float sg6 = ((__popc(t & 6) & 1) ? -1.0f : 1.0f);
    float sg7 = ((__popc(t & 7) & 1) ? -1.0f : 1.0f);

    float r[8];
    r[0] = sg3 * S1F;   // mask 0x7F
    r[1] = sg6 * S00;   // mask 0xC0
    r[2] = sg7 * S00;   // mask 0xE0
    r[3] = sg7 * S10;   // 0xF0
    r[4] = sg7 * S18;   // 0xF8
    r[5] = sg7 * S1C;   // 0xFC
    r[6] = sg7 * S1E;   // 0xFE
    r[7] = sg7 * S1F;   // 0xFF

#pragma unroll
    for (int d = 1; d < 8; d <<= 1) {
#pragma unroll
        for (int i = 0; i < 8; i++)
            r[i] += __shfl_xor_sync(FULL, r[i], d);
    }

    if (valid) {
#pragma unroll
        for (int k = 0; k < 8; k++)
            if (t == k) out[b * 8 + k] = r[k];
    }
}

extern "C" void kernel_launch(void* const* d_in, const int* in_sizes, int n_in,
                              void* d_out, int out_size)
{
    const float* x = (const float*)d_in[0];
    const float* w = (const float*)d_in[1];
    float* out = (float*)d_out;
    int B = in_sizes[0] / 8;

    qnn_setup<<<1, 32>>>(w);

    int warps = (B + 3) / 4;
    int blocks = (warps + 7) / 8;
    qnn_main<<<blocks, 256>>>(x, out, B);
}

// round 3
// speedup vs baseline: 1.6262x; 1.4164x over previous
#include <cuda_runtime.h>

#define DEVINL __device__ __forceinline__

typedef unsigned long long u64;

struct cplx { float x, y; };

DEVINL cplx cmul(cplx a, cplx b) {
    cplx r;
    r.x = fmaf(a.x, b.x, -a.y * b.y);
    r.y = fmaf(a.x, b.y,  a.y * b.x);
    return r;
}
// acc + a*b
DEVINL cplx cfma(cplx a, cplx b, cplx acc) {
    acc.x = fmaf(a.x, b.x, fmaf(-a.y, b.y, acc.x));
    acc.y = fmaf(a.x, b.y, fmaf( a.y, b.x, acc.y));
    return acc;
}

// ---- packed f32x2 helpers ----
DEVINL u64 pk(float lo, float hi) {
    u64 r; asm("mov.b64 %0,{%1,%2};" : "=l"(r) : "f"(lo), "f"(hi)); return r;
}
DEVINL void upk(u64 a, float& lo, float& hi) {
    asm("mov.b64 {%0,%1},%2;" : "=f"(lo), "=f"(hi) : "l"(a));
}
DEVINL u64 spl(float v) { return pk(v, v); }
DEVINL u64 fma2(u64 a, u64 b, u64 c) {
    u64 r; asm("fma.rn.f32x2 %0,%1,%2,%3;" : "=l"(r) : "l"(a), "l"(b), "l"(c)); return r;
}
DEVINL u64 mul2(u64 a, u64 b) {
    u64 r; asm("mul.rn.f32x2 %0,%1,%2;" : "=l"(r) : "l"(a), "l"(b)); return r;
}
DEVINL u64 add2(u64 a, u64 b) {
    u64 r; asm("add.rn.f32x2 %0,%1,%2;" : "=l"(r) : "l"(a), "l"(b)); return r;
}
DEVINL u64 neg2(u64 a) { return a ^ 0x8000000080000000ULL; }
DEVINL u64 swp(u64 a) { float x, y; upk(a, x, y); return pk(y, x); }

// fused U[layer][qubit] = RZ(w2)*RY(w1)*RX(w0):
// u00.x u00.y u01.x u01.y u10.x u10.y u11.x u11.y
__device__ float g_U[2][8][8];

__global__ void qnn_setup(const float* __restrict__ w) {
    int i = threadIdx.x;
    if (i >= 16) return;
    int l = i >> 3, q = i & 7;
    float a = w[(l * 8 + q) * 3 + 0];
    float b = w[(l * 8 + q) * 3 + 1];
    float c = w[(l * 8 + q) * 3 + 2];
    float sa, ca; sincosf(0.5f * a, &sa, &ca);
    float sb, cb; sincosf(0.5f * b, &sb, &cb);
    float sc, cc; sincosf(0.5f * c, &sc, &cc);
    cplx m00 = {  cb * ca,  sb * sa };
    cplx m01 = { -sb * ca, -cb * sa };
    cplx m10 = {  sb * ca, -cb * sa };
    cplx m11 = {  cb * ca, -sb * sa };
    cplx e0 = { cc, -sc };
    cplx e1 = { cc,  sc };
    cplx u00 = cmul(e0, m00), u01 = cmul(e0, m01);
    cplx u10 = cmul(e1, m10), u11 = cmul(e1, m11);
    float* dst = g_U[l][q];
    dst[0] = u00.x; dst[1] = u00.y; dst[2] = u01.x; dst[3] = u01.y;
    dst[4] = u10.x; dst[5] = u10.y; dst[6] = u11.x; dst[7] = u11.y;
}

// Layout: 8 lanes per sample (g = lane>>3, t = lane&7).
// Full amp index bits [7..0] = [t2 t1 t0 | j4 j3 j2 j1 | j0], wire w <-> bit 7-w.
// Per lane: 16 packed (over j0) complex amps, k = (j4<<3)|(j3<<2)|(j2<<1)|j1.
__global__ void __launch_bounds__(256) qnn_main(
    const float* __restrict__ x, float* __restrict__ out, int B)
{
    const unsigned FULL = 0xffffffffu;
    int L = threadIdx.x & 31;
    int warp = blockIdx.x * (blockDim.x >> 5) + (threadIdx.x >> 5);
    int g = L >> 3;
    int t = L & 7;
    int b = warp * 4 + g;
    bool valid = (b < B);

    float xv = valid ? x[b * 8 + t] : 0.0f;
    float s, c;
    __sincosf(0.5f * xv, &s, &c);

    // V_q = U[0][q]*RX(x_q) column 0 (embedding fused into layer-0).
    const float* u0 = g_U[0][t];
    cplx myv0, myv1;
    myv0.x = fmaf(c, u0[0],  s * u0[3]);
    myv0.y = fmaf(c, u0[1], -s * u0[2]);
    myv1.x = fmaf(c, u0[4],  s * u0[7]);
    myv1.y = fmaf(c, u0[5], -s * u0[6]);

    cplx va[8], vb[8];
    int base = L & ~7;
#pragma unroll
    for (int q = 0; q < 8; q++) {
        int src = base | q;
        va[q].x = __shfl_sync(FULL, myv0.x, src);
        va[q].y = __shfl_sync(FULL, myv0.y, src);
        vb[q].x = __shfl_sync(FULL, myv1.x, src);
        vb[q].y = __shfl_sync(FULL, myv1.y, src);
    }

    int a_ = (t >> 2) & 1, b_ = (t >> 1) & 1, c_ = t & 1;   // t2,t1,t0

    // ============================================================
    // Symbolic application of layer-1 gates on wires 0,1,2 to
    // T(a,b,c; j0,j4) = v0[a^j0] v1[a^b^j0] v2[b^c] v3[c^j4].
    // Result P[j0][j4] for this lane's (a,b,c). No shuffles needed.
    // ============================================================
    const float* u0g = g_U[1][0];
    const float* u1g = g_U[1][1];
    const float* u2g = g_U[1][2];
    cplx C0 = { u2g[4*c_ + 0], u2g[4*c_ + 1] };   // U2[c][0]
    cplx C1 = { u2g[4*c_ + 2], u2g[4*c_ + 3] };   // U2[c][1]
    cplx B0 = { u1g[4*b_ + 0], u1g[4*b_ + 1] };   // U1[b][0]
    cplx B1 = { u1g[4*b_ + 2], u1g[4*b_ + 3] };   // U1[b][1]
    cplx A0 = { u0g[4*a_ + 0], u0g[4*a_ + 1] };   // U0[a][0]
    cplx A1 = { u0g[4*a_ + 2], u0g[4*a_ + 3] };   // U0[a][1]

    // w[s][r] = U2[c][s] * v2[r^s]
    cplx w00 = cmul(C0, va[2]);   // s=0,r=0
    cplx w01 = cmul(C0, vb[2]);   // s=0,r=1
    cplx w10 = cmul(C1, vb[2]);   // s=1,r=0
    cplx w11 = cmul(C1, va[2]);   // s=1,r=1
    // z[r][e] = U1[b][r] * v1[e^r]
    cplx z00 = cmul(B0, va[1]);   // r=0,e=0
    cplx z01 = cmul(B0, vb[1]);   // r=0,e=1
    cplx z10 = cmul(B1, vb[1]);   // r=1,e=0
    cplx z11 = cmul(B1, va[1]);   // r=1,e=1

    // packed over j4: V3s0 = (v3[j4]) ; V3s1 = (v3[1^j4])
    u64 V30X = pk(va[3].x, vb[3].x), V30Y = pk(va[3].y, vb[3].y);
    u64 V31X = swp(V30X),            V31Y = swp(V30Y);

    // M[r] = w[0][r] (x) V3s0 + w[1][r] (x) V3s1   (packed over j4)
    u64 MX[2], MY[2];
#pragma unroll
    for (int r = 0; r < 2; r++) {
        cplx s0 = r ? w01 : w00;
        cplx s1 = r ? w11 : w10;
        MX[r] = fma2(spl(s0.x), V30X, fma2(spl(-s0.y), V30Y,
                 fma2(spl(s1.x), V31X, mul2(spl(-s1.y), V31Y))));
        MY[r] = fma2(spl(s0.x), V30Y, fma2(spl(s0.y), V30X,
                 fma2(spl(s1.x), V31Y, mul2(spl(s1.y), V31X))));
    }
    // N[e] = z[0][e] (x) M[0] + z[1][e] (x) M[1]
    u64 NX[2], NY[2];
#pragma unroll
    for (int e = 0; e < 2; e++) {
        cplx s0 = e ? z01 : z00;
        cplx s1 = e ? z11 : z10;
        NX[e] = fma2(spl(s0.x), MX[0], fma2(spl(-s0.y), MY[0],
                 fma2(spl(s1.x), MX[1], mul2(spl(-s1.y), MY[1]))));
        NY[e] = fma2(spl(s0.x), MY[0], fma2(spl(s0.y), MX[0],
                 fma2(spl(s1.x), MY[1], mul2(spl(s1.y), MX[1]))));
    }
    // R[e] = v0[e] (x) N[e]
    u64 RX[2], RY[2];
#pragma unroll
    for (int e = 0; e < 2; e++) {
        cplx v = e ? vb[0] : va[0];
        RX[e] = fma2(spl(v.x), NX[e], mul2(spl(-v.y), NY[e]));
        RY[e] = fma2(spl(v.x), NY[e], mul2(spl(v.y), NX[e]));
    }
    // P[j0] = A0 (x) R[j0] + A1 (x) R[j0^1]   (still packed over j4)
    u64 PX[2], PY[2];
#pragma unroll
    for (int j0 = 0; j0 < 2; j0++) {
        PX[j0] = fma2(spl(A0.x), RX[j0], fma2(spl(-A0.y), RY[j0],
                   fma2(spl(A1.x), RX[j0 ^ 1], mul2(spl(-A1.y), RY[j0 ^ 1]))));
        PY[j0] = fma2(spl(A0.x), RY[j0], fma2(spl(A0.y), RX[j0],
                   fma2(spl(A1.x), RY[j0 ^ 1], mul2(spl(A1.y), RX[j0 ^ 1]))));
    }
    // transpose to packed-over-j0: Q[j4] = (P[0][j4], P[1][j4])
    u64 QX[2], QY[2];
    {
        float p00, p01, p10, p11;
        upk(PX[0], p00, p01); upk(PX[1], p10, p11);
        QX[0] = pk(p00, p10); QX[1] = pk(p01, p11);
        upk(PY[0], p00, p01); upk(PY[1], p10, p11);
        QY[0] = pk(p00, p10); QY[1] = pk(p01, p11);
    }

    // PV[j1][j4] = Q[j4] (x) V7[j1],  V7[j1] = (v7[j1^j0]) packed over j0
    u64 V7X[2], V7Y[2];
    V7X[0] = pk(va[7].x, vb[7].x); V7Y[0] = pk(va[7].y, vb[7].y);
    V7X[1] = swp(V7X[0]);          V7Y[1] = swp(V7Y[0]);
    u64 nQY0 = neg2(QY[0]), nQY1 = neg2(QY[1]);
    u64 PVX[2][2], PVY[2][2];
#pragma unroll
    for (int j1 = 0; j1 < 2; j1++) {
#pragma unroll
        for (int j4 = 0; j4 < 2; j4++) {
            u64 nqy = j4 ? nQY1 : nQY0;
            PVX[j1][j4] = fma2(QX[j4], V7X[j1], mul2(nqy, V7Y[j1]));
            PVY[j1][j4] = fma2(QX[j4], V7Y[j1], mul2(QY[j4], V7X[j1]));
        }
    }

    // chain tree over (j4,j3,j2,j1): v4[j4^j3] v5[j3^j2] v6[j2^j1]
    cplx tt[4];
    tt[0] = va[4]; tt[1] = vb[4]; tt[2] = vb[4]; tt[3] = va[4];
    cplx t3[8];
#pragma unroll
    for (int i = 0; i < 8; i++)
        t3[i] = cmul(tt[i >> 1], (((i >> 1) & 1) ^ (i & 1)) ? vb[5] : va[5]);
    cplx t4[16];
#pragma unroll
    for (int i = 0; i < 16; i++)
        t4[i] = cmul(t3[i >> 1], (((i >> 1) & 1) ^ (i & 1)) ? vb[6] : va[6]);

    // amp[k] (packed over j0) = t4[k] * PV[j1][j4]
    u64 X[16], Y[16];
#pragma unroll
    for (int k = 0; k < 16; k++) {
        int j1 = k & 1, j4 = (k >> 3) & 1;
        u64 sx = spl(t4[k].x), sy = spl(t4[k].y), nsy = spl(-t4[k].y);
        X[k] = fma2(sx, PVX[j1][j4], mul2(nsy, PVY[j1][j4]));
        Y[k] = fma2(sx, PVY[j1][j4], mul2(sy, PVX[j1][j4]));
    }

    // ---- remaining layer-1 gates: wires 3..6 local, wire 7 packed ----
#pragma unroll
    for (int q = 3; q < 7; q++) {
        const float* u = g_U[1][q];
        u64 u00x = spl(u[0]), u00y = spl(u[1]), n00y = spl(-u[1]);
        u64 u01x = spl(u[2]), u01y = spl(u[3]), n01y = spl(-u[3]);
        u64 u10x = spl(u[4]), u10y = spl(u[5]), n10y = spl(-u[5]);
        u64 u11x = spl(u[6]), u11y = spl(u[7]), n11y = spl(-u[7]);
        int m = 1 << (6 - q);
#pragma unroll
        for (int k = 0; k < 16; k++) {
            if ((k & m) == 0) {
                u64 X0 = X[k], Y0 = Y[k], X1 = X[k + m], Y1 = Y[k + m];
                X[k]     = fma2(u00x, X0, fma2(n00y, Y0, fma2(u01x, X1, mul2(n01y, Y1))));
                Y[k]     = fma2(u00x, Y0, fma2(u00y, X0, fma2(u01x, Y1, mul2(u01y, X1))));
                X[k + m] = fma2(u10x, X0, fma2(n10y, Y0, fma2(u11x, X1, mul2(n11y, Y1))));
                Y[k + m] = fma2(u10x, Y0, fma2(u10y, X0, fma2(u11x, Y1, mul2(u11y, X1))));
            }
        }
    }
    {   // wire 7 = packed dimension j0
        const float* u = g_U[1][7];
        u64 CAx = pk(u[0], u[6]), CAy = pk(u[1], u[7]), nCAy = pk(-u[1], -u[7]);
        u64 CBx = pk(u[2], u[4]), CBy = pk(u[3], u[5]), nCBy = pk(-u[3], -u[5]);
#pragma unroll
        for (int k = 0; k < 16; k++) {
            u64 X0 = X[k], Y0 = Y[k];
            u64 Xs = swp(X0), Ys = swp(Y0);
            X[k] = fma2(CAx, X0, fma2(nCAy, Y0, fma2(CBx, Xs, mul2(nCBy, Ys))));
            Y[k] = fma2(CAx, Y0, fma2(CAy, X0, fma2(CBx, Ys, mul2(CBy, Xs))));
        }
    }

    // ---- measurement: packed parity-sum tree (final ring folded in) ----
    u64 PR[16];
#pragma unroll
    for (int k = 0; k < 16; k++)
        PR[k] = fma2(X[k], X[k], mul2(Y[k], Y[k]));

    u64 m1 = spl(-1.0f);
    u64 SP[8], DP[8];
#pragma unroll
    for (int h = 0; h < 8; h++) {            // combine j1
        SP[h] = add2(PR[2*h], PR[2*h+1]);
        DP[h] = fma2(m1, PR[2*h+1], PR[2*h]);
    }
    u64 S2[4], A2[4], B2[4];
#pragma unroll
    for (int h = 0; h < 4; h++) {            // combine j2
        S2[h] = add2(SP[2*h], SP[2*h+1]);
        A2[h] = fma2(m1, SP[2*h+1], SP[2*h]);
        B2[h] = fma2(m1, DP[2*h+1], DP[2*h]);
    }
    u64 S3[2], C3[2], A3[2], B3[2];
#pragma unroll
    for (int h = 0; h < 2; h++) {            // combine j3
        S3[h] = add2(S2[2*h], S2[2*h+1]);
        C3[h] = fma2(m1, S2[2*h+1], S2[2*h]);
        A3[h] = fma2(m1, A2[2*h+1], A2[2*h]);
        B3[h] = fma2(m1, B2[2*h+1], B2[2*h]);
    }
    u64 S4 = add2(S3[0], S3[1]);             // combine j4
    u64 E4 = fma2(m1, S3[1], S3[0]);
    u64 C4 = fma2(m1, C3[1], C3[0]);
    u64 A4 = fma2(m1, A3[1], A3[0]);
    u64 B4 = fma2(m1, B3[1], B3[0]);

    float lo, hi;
    upk(S4, lo, hi); float S00 = lo + hi;
    upk(E4, lo, hi); float S10 = lo + hi;
    upk(C4, lo, hi); float S18 = lo + hi;
    upk(A4, lo, hi); float S1C = lo + hi;
    upk(B4, lo, hi); float S1E = lo + hi, S1F = lo - hi;

    float sg3 = ((__popc(t & 3) & 1) ? -1.0f : 1.0f);
    float sg6 = ((__popc(t & 6) & 1) ? -1.0f : 1.0f);
    float sg7 = ((__popc(t & 7) & 1) ? -1.0f : 1.0f);

    float r[8];
    r[0] = sg3 * S1F;   // Z0: mask 0x7F
    r[1] = sg6 * S00;   // Z1: mask 0xC0
    r[2] = sg7 * S00;   // Z2: mask 0xE0
    r[3] = sg7 * S10;   // 0xF0
    r[4] = sg7 * S18;   // 0xF8
    r[5] = sg7 * S1C;   // 0xFC
    r[6] = sg7 * S1E;   // 0xFE
    r[7] = sg7 * S1F;   // 0xFF

    // distributed transpose-reduction across the 8-lane group (7 shfls)
    int t0 = c_, t1 = b_, t2 = a_;
    float q4[4];
#pragma unroll
    for (int j = 0; j < 4; j++) {
        float keep = t0 ? r[2*j+1] : r[2*j];
        float send = t0 ? r[2*j]   : r[2*j+1];
        q4[j] = keep + __shfl_xor_sync(FULL, send, 1);
    }
    float q2[2];
#pragma unroll
    for (int j = 0; j < 2; j++) {
        float keep = t1 ? q4[2*j+1] : q4[2*j];
        float send = t1 ? q4[2*j]   : q4[2*j+1];
        q2[j] = keep + __shfl_xor_sync(FULL, send, 2);
    }
    float keep = t2 ? q2[1] : q2[0];
    float send = t2 ? q2[0] : q2[1];
    float res = keep + __shfl_xor_sync(FULL, send, 4);

    if (valid) out[b * 8 + t] = res;
}

extern "C" void kernel_launch(void* const* d_in, const int* in_sizes, int n_in,
                              void* d_out, int out_size)
{
    const float* x = (const float*)d_in[0];
    const float* w = (const float*)d_in[1];
    float* out = (float*)d_out;
    int B = in_sizes[0] / 8;

    qnn_setup<<<1, 32>>>(w);

    int warps = (B + 3) / 4;
    int blocks = (warps + 7) / 8;
    qnn_main<<<blocks, 256>>>(x, out, B);
}

// round 5
// speedup vs baseline: 1.6393x; 1.0080x over previous
#include <cuda_runtime.h>

#define DEVINL __device__ __forceinline__

typedef unsigned long long u64;

struct cplx { float x, y; };

DEVINL cplx cmul(cplx a, cplx b) {
    cplx r;
    r.x = fmaf(a.x, b.x, -a.y * b.y);
    r.y = fmaf(a.x, b.y,  a.y * b.x);
    return r;
}

// ---- packed f32x2 helpers ----
DEVINL u64 pk(float lo, float hi) {
    u64 r; asm("mov.b64 %0,{%1,%2};" : "=l"(r) : "f"(lo), "f"(hi)); return r;
}
DEVINL void upk(u64 a, float& lo, float& hi) {
    asm("mov.b64 {%0,%1},%2;" : "=f"(lo), "=f"(hi) : "l"(a));
}
DEVINL u64 spl(float v) { return pk(v, v); }
DEVINL u64 fma2(u64 a, u64 b, u64 c) {
    u64 r; asm("fma.rn.f32x2 %0,%1,%2,%3;" : "=l"(r) : "l"(a), "l"(b), "l"(c)); return r;
}
DEVINL u64 mul2(u64 a, u64 b) {
    u64 r; asm("mul.rn.f32x2 %0,%1,%2;" : "=l"(r) : "l"(a), "l"(b)); return r;
}
DEVINL u64 add2(u64 a, u64 b) {
    u64 r; asm("add.rn.f32x2 %0,%1,%2;" : "=l"(r) : "l"(a), "l"(b)); return r;
}
DEVINL u64 neg2(u64 a) { return a ^ 0x8000000080000000ULL; }
DEVINL u64 swp(u64 a) { float x, y; upk(a, x, y); return pk(y, x); }

// g_U[0][q]: full RZ*RY*RX (layer 0).
// g_U[1][q]: RY*RX only (layer-1 RZ phases provably drop out: only a basis
//            permutation + |.|^2 follow). SU(2) form [[a,b],[-b*,a*]].
// 8 floats: u00.x u00.y u01.x u01.y u10.x u10.y u11.x u11.y
__device__ float g_U[2][8][8];

__global__ void qnn_setup(const float* __restrict__ w) {
    int i = threadIdx.x;
    if (i >= 16) return;
    int l = i >> 3, q = i & 7;
    float a = w[(l * 8 + q) * 3 + 0];
    float b = w[(l * 8 + q) * 3 + 1];
    float c = w[(l * 8 + q) * 3 + 2];
    float sa, ca; sincosf(0.5f * a, &sa, &ca);
    float sb, cb; sincosf(0.5f * b, &sb, &cb);
    float sc, cc; sincosf(0.5f * c, &sc, &cc);
    cplx m00 = {  cb * ca,  sb * sa };
    cplx m01 = { -sb * ca, -cb * sa };
    cplx m10 = {  sb * ca, -cb * sa };
    cplx m11 = {  cb * ca, -sb * sa };
    cplx u00, u01, u10, u11;
    if (l == 0) {
        cplx e0 = { cc, -sc };
        cplx e1 = { cc,  sc };
        u00 = cmul(e0, m00); u01 = cmul(e0, m01);
        u10 = cmul(e1, m10); u11 = cmul(e1, m11);
    } else {
        u00 = m00; u01 = m01; u10 = m10; u11 = m11;   // RZ dropped
    }
    float* dst = g_U[l][q];
    dst[0] = u00.x; dst[1] = u00.y; dst[2] = u01.x; dst[3] = u01.y;
    dst[4] = u10.x; dst[5] = u10.y; dst[6] = u11.x; dst[7] = u11.y;
}

// Layout: 8 lanes per sample (g = lane>>3, t = lane&7).
// Full amp index bits [7..0] = [t2 t1 t0 | j4 j3 j2 j1 | j0], wire w <-> bit 7-w.
// Per lane: 16 packed (over j0) complex amps, k = (j4<<3)|(j3<<2)|(j2<<1)|j1.
__global__ void __launch_bounds__(256, 3) qnn_main(
    const float* __restrict__ x, float* __restrict__ out, int B)
{
    const unsigned FULL = 0xffffffffu;
    int L = threadIdx.x & 31;
    int warp = blockIdx.x * (blockDim.x >> 5) + (threadIdx.x >> 5);
    int g = L >> 3;
    int t = L & 7;
    int b = warp * 4 + g;
    bool valid = (b < B);

    float xv = valid ? x[b * 8 + t] : 0.0f;
    float s, c;
    __sincosf(0.5f * xv, &s, &c);

    // V_q = U[0][q]*RX(x_q) column 0 (embedding fused into layer-0).
    const float* u0 = g_U[0][t];
    cplx myv0, myv1;
    myv0.x = fmaf(c, u0[0],  s * u0[3]);
    myv0.y = fmaf(c, u0[1], -s * u0[2]);
    myv1.x = fmaf(c, u0[4],  s * u0[7]);
    myv1.y = fmaf(c, u0[5], -s * u0[6]);

    cplx va[8], vb[8];
    int base = L & ~7;
#pragma unroll
    for (int q = 0; q < 8; q++) {
        int src = base | q;
        va[q].x = __shfl_sync(FULL, myv0.x, src);
        va[q].y = __shfl_sync(FULL, myv0.y, src);
        vb[q].x = __shfl_sync(FULL, myv1.x, src);
        vb[q].y = __shfl_sync(FULL, myv1.y, src);
    }

    int a_ = (t >> 2) & 1, b_ = (t >> 1) & 1, c_ = t & 1;   // t2,t1,t0

    // ============================================================
    // Symbolic application of layer-1 gates on wires 0,1,2,3 to the
    // product state (CNOT ring re-associated as XOR args):
    // amp = v0[a'^j0] v1[a'^b'^j0] v2[b'^c'] v3[c'^d'] v4[d'^j3]
    //       * v5[j3^j2] v6[j2^j1] v7[j1^j0]
    // Result P[j0][j3] packed over j4 (= output bit of wire 3).
    // ============================================================
    const float* u0g = g_U[1][0];
    const float* u1g = g_U[1][1];
    const float* u2g = g_U[1][2];
    const float* u3g = g_U[1][3];
    cplx C0 = { u2g[4*c_ + 0], u2g[4*c_ + 1] };   // U2[c][0]
    cplx C1 = { u2g[4*c_ + 2], u2g[4*c_ + 3] };   // U2[c][1]
    cplx B0 = { u1g[4*b_ + 0], u1g[4*b_ + 1] };   // U1[b][0]
    cplx B1 = { u1g[4*b_ + 2], u1g[4*b_ + 3] };   // U1[b][1]
    cplx A0 = { u0g[4*a_ + 0], u0g[4*a_ + 1] };   // U0[a][0]
    cplx A1 = { u0g[4*a_ + 2], u0g[4*a_ + 3] };   // U0[a][1]

    // w[s][r] = U2[c][s] * v2[r^s]
    cplx w00 = cmul(C0, va[2]);
    cplx w01 = cmul(C0, vb[2]);
    cplx w10 = cmul(C1, vb[2]);
    cplx w11 = cmul(C1, va[2]);
    // z[r][e] = U1[b][r] * v1[e^r]
    cplx z00 = cmul(B0, va[1]);
    cplx z01 = cmul(B0, vb[1]);
    cplx z10 = cmul(B1, vb[1]);
    cplx z11 = cmul(B1, va[1]);

    // packed over j4': V3s0 = v3[j4'], V3s1 = v3[1^j4']
    u64 V30X = pk(va[3].x, vb[3].x), V30Y = pk(va[3].y, vb[3].y);
    u64 V31X = swp(V30X),            V31Y = swp(V30Y);

    // M[r](j4') = sum_s w[s][r] v3[s^j4']
    u64 MX[2], MY[2];
#pragma unroll
    for (int r = 0; r < 2; r++) {
        cplx s0 = r ? w01 : w00;
        cplx s1 = r ? w11 : w10;
        MX[r] = fma2(spl(s0.x), V30X, fma2(spl(-s0.y), V30Y,
                 fma2(spl(s1.x), V31X, mul2(spl(-s1.y), V31Y))));
        MY[r] = fma2(spl(s0.x), V30Y, fma2(spl(s0.y), V30X,
                 fma2(spl(s1.x), V31Y, mul2(spl(s1.y), V31X))));
    }

    // mj[r][j3](j4') = M[r](j4') * v4[j4'^j3]
    u64 V40X = pk(va[4].x, vb[4].x), V40Y = pk(va[4].y, vb[4].y);
    u64 V41X = swp(V40X),            V41Y = swp(V40Y);
    // then g[r][j3](j4) = sum_{j4'} U3[j4,j4'] mj[r][j3](j4')
    // U3 SU(2): alpha=(u[0],u[1]), beta=(u[2],u[3])
    u64 T0x = spl(u3g[0]);
    u64 T0y = pk(u3g[1], -u3g[1]);
    u64 nT0y = neg2(T0y);
    u64 T1x = pk(u3g[2], -u3g[2]);
    u64 T1y = spl(u3g[3]);
    u64 nT1y = neg2(T1y);
    u64 GX[2][2], GY[2][2];
#pragma unroll
    for (int r = 0; r < 2; r++) {
#pragma unroll
        for (int j3 = 0; j3 < 2; j3++) {
            u64 vx = j3 ? V41X : V40X, vy = j3 ? V41Y : V40Y;
            u64 mX = fma2(MX[r], vx, mul2(neg2(MY[r]), vy));
            u64 mY = fma2(MX[r], vy, mul2(MY[r], vx));
            u64 smX = swp(mX), smY = swp(mY);
            GX[r][j3] = fma2(T0x, mX, fma2(nT0y, mY, fma2(T1x, smX, mul2(nT1y, smY))));
            GY[r][j3] = fma2(T0x, mY, fma2(T0y, mX, fma2(T1x, smY, mul2(T1y, smX))));
        }
    }

    // N[e][j3] = sum_r z[r][e] (x) g[r][j3]
    u64 NX[2][2], NY[2][2];
#pragma unroll
    for (int e = 0; e < 2; e++) {
        cplx s0 = e ? z01 : z00;
        cplx s1 = e ? z11 : z10;
        u64 s0x = spl(s0.x), ns0y = spl(-s0.y), s0y = spl(s0.y);
        u64 s1x = spl(s1.x), ns1y = spl(-s1.y), s1y = spl(s1.y);
#pragma unroll
        for (int j3 = 0; j3 < 2; j3++) {
            NX[e][j3] = fma2(s0x, GX[0][j3], fma2(ns0y, GY[0][j3],
                         fma2(s1x, GX[1][j3], mul2(ns1y, GY[1][j3]))));
            NY[e][j3] = fma2(s0x, GY[0][j3], fma2(s0y, GX[0][j3],
                         fma2(s1x, GY[1][j3], mul2(s1y, GX[1][j3]))));
        }
    }
    // R[e][j3] = v0[e] (x) N[e][j3]
    u64 RXa[2][2], RYa[2][2];
#pragma unroll
    for (int e = 0; e < 2; e++) {
        cplx v = e ? vb[0] : va[0];
        u64 vx = spl(v.x), nvy = spl(-v.y), vy = spl(v.y);
#pragma unroll
        for (int j3 = 0; j3 < 2; j3++) {
            RXa[e][j3] = fma2(vx, NX[e][j3], mul2(nvy, NY[e][j3]));
            RYa[e][j3] = fma2(vx, NY[e][j3], mul2(vy, NX[e][j3]));
        }
    }
    // P[j0][j3] = A0 (x) R[j0][j3] + A1 (x) R[j0^1][j3]  (packed over j4)
    u64 PX[2][2], PY[2][2];
    {
        u64 a0x = spl(A0.x), na0y = spl(-A0.y), a0y = spl(A0.y);
        u64 a1x = spl(A1.x), na1y = spl(-A1.y), a1y = spl(A1.y);
#pragma unroll
        for (int j0 = 0; j0 < 2; j0++) {
#pragma unroll
            for (int j3 = 0; j3 < 2; j3++) {
                PX[j0][j3] = fma2(a0x, RXa[j0][j3], fma2(na0y, RYa[j0][j3],
                              fma2(a1x, RXa[j0^1][j3], mul2(na1y, RYa[j0^1][j3]))));
                PY[j0][j3] = fma2(a0x, RYa[j0][j3], fma2(a0y, RXa[j0][j3],
                              fma2(a1x, RYa[j0^1][j3], mul2(a1y, RXa[j0^1][j3]))));
            }
        }
    }
    // transpose to packed-over-j0: Q[j4][j3]
    u64 QX[2][2], QY[2][2];
#pragma unroll
    for (int j3 = 0; j3 < 2; j3++) {
        float p00, p01, p10, p11;
        upk(PX[0][j3], p00, p01); upk(PX[1][j3], p10, p11);
        QX[0][j3] = pk(p00, p10); QX[1][j3] = pk(p01, p11);
        upk(PY[0][j3], p00, p01); upk(PY[1][j3], p10, p11);
        QY[0][j3] = pk(p00, p10); QY[1][j3] = pk(p01, p11);
    }

    // PV[j1][j4][j3] = Q[j4][j3] (x) V7[j1],  V7[j1](j0) = v7[j1^j0]
    u64 V7X[2], V7Y[2];
    V7X[0] = pk(va[7].x, vb[7].x); V7Y[0] = pk(va[7].y, vb[7].y);
    V7X[1] = swp(V7X[0]);          V7Y[1] = swp(V7Y[0]);
    u64 PVX[2][2][2], PVY[2][2][2];
#pragma unroll
    for (int j4 = 0; j4 < 2; j4++) {
#pragma unroll
        for (int j3 = 0; j3 < 2; j3++) {
            u64 nqy = neg2(QY[j4][j3]);
#pragma unroll
            for (int j1 = 0; j1 < 2; j1++) {
                PVX[j1][j4][j3] = fma2(QX[j4][j3], V7X[j1], mul2(nqy, V7Y[j1]));
                PVY[j1][j4][j3] = fma2(QX[j4][j3], V7Y[j1], mul2(QY[j4][j3], V7X[j1]));
            }
        }
    }

    // chain tc[j3][j2][j1] = v5[j3^j2] * v6[j2^j1]
    cplx tc[2][2][2];
#pragma unroll
    for (int j3 = 0; j3 < 2; j3++)
#pragma unroll
        for (int j2 = 0; j2 < 2; j2++) {
            cplx f5 = (j3 ^ j2) ? vb[5] : va[5];
#pragma unroll
            for (int j1 = 0; j1 < 2; j1++)
                tc[j3][j2][j1] = cmul(f5, (j2 ^ j1) ? vb[6] : va[6]);
        }

    // amp[k] (packed over j0) = tc * PV
    u64 X[16], Y[16];
#pragma unroll
    for (int k = 0; k < 16; k++) {
        int j4 = (k >> 3) & 1, j3 = (k >> 2) & 1, j2 = (k >> 1) & 1, j1 = k & 1;
        cplx tcv = tc[j3][j2][j1];
        u64 sx = spl(tcv.x), sy = spl(tcv.y), nsy = spl(-tcv.y);
        X[k] = fma2(sx, PVX[j1][j4][j3], mul2(nsy, PVY[j1][j4][j3]));
        Y[k] = fma2(sx, PVY[j1][j4][j3], mul2(sy, PVX[j1][j4][j3]));
    }

    // ---- layer-1 gates: wires 4..6 local sweeps (SU(2)), wire 7 packed ----
#pragma unroll
    for (int q = 4; q < 7; q++) {
        const float* u = g_U[1][q];
        u64 ax = spl(u[0]), ay = spl(u[1]), nay = spl(-u[1]);
        u64 bx = spl(u[2]), by = spl(u[3]), nby = spl(-u[3]);
        u64 nbx = spl(-u[2]);
        int m = 1 << (6 - q);
#pragma unroll
        for (int k = 0; k < 16; k++) {
            if ((k & m) == 0) {
                u64 X0 = X[k], Y0 = Y[k], X1 = X[k + m], Y1 = Y[k + m];
                X[k]     = fma2(ax, X0, fma2(nay, Y0, fma2(bx, X1, mul2(nby, Y1))));
                Y[k]     = fma2(ax, Y0, fma2(ay, X0, fma2(bx, Y1, mul2(by, X1))));
                X[k + m] = fma2(nbx, X0, fma2(nby, Y0, fma2(ax, X1, mul2(ay, Y1))));
                Y[k + m] = fma2(nbx, Y0, fma2(by, X0, fma2(ax, Y1, mul2(nay, X1))));
            }
        }
    }
    {   // wire 7 = packed dimension j0 (SU(2))
        const float* u = g_U[1][7];
        u64 CAx = spl(u[0]);
        u64 CAy = pk(u[1], -u[1]);
        u64 nCAy = neg2(CAy);
        u64 CBx = pk(u[2], -u[2]);
        u64 CBy = spl(u[3]);
        u64 nCBy = spl(-u[3]);
#pragma unroll
        for (int k = 0; k < 16; k++) {
            u64 X0 = X[k], Y0 = Y[k];
            u64 Xs = swp(X0), Ys = swp(Y0);
            X[k] = fma2(CAx, X0, fma2(nCAy, Y0, fma2(CBx, Xs, mul2(nCBy, Ys))));
            Y[k] = fma2(CAx, Y0, fma2(CAy, X0, fma2(CBx, Ys, mul2(CBy, Xs))));
        }
    }

    // ---- measurement: packed parity-sum tree (final ring folded in) ----
    u64 PR[16];
#pragma unroll
    for (int k = 0; k < 16; k++)
        PR[k] = fma2(X[k], X[k], mul2(Y[k], Y[k]));

    u64 m1 = spl(-1.0f);
    u64 SP[8], DP[8];
#pragma unroll
    for (int h = 0; h < 8; h++) {            // combine j1
        SP[h] = add2(PR[2*h], PR[2*h+1]);
        DP[h] = fma2(m1, PR[2*h+1], PR[2*h]);
    }
    u64 S2[4], A2[4], B2[4];
#pragma unroll
    for (int h = 0; h < 4; h++) {            // combine j2
        S2[h] = add2(SP[2*h], SP[2*h+1]);
        A2[h] = fma2(m1, SP[2*h+1], SP[2*h]);
        B2[h] = fma2(m1, DP[2*h+1], DP[2*h]);
    }
    u64 S3[2], C3[2], A3[2], B3[2];
#pragma unroll
    for (int h = 0; h < 2; h++) {            // combine j3
        S3[h] = add2(S2[2*h], S2[2*h+1]);
        C3[h] = fma2(m1, S2[2*h+1], S2[2*h]);
        A3[h] = fma2(m1, A2[2*h+1], A2[2*h]);
        B3[h] = fma2(m1, B2[2*h+1], B2[2*h]);
    }
    u64 S4 = add2(S3[0], S3[1]);             // combine j4
    u64 E4 = fma2(m1, S3[1], S3[0]);
    u64 C4 = fma2(m1, C3[1], C3[0]);
    u64 A4 = fma2(m1, A3[1], A3[0]);
    u64 B4 = fma2(m1, B3[1], B3[0]);

    float lo, hi;
    upk(S4, lo, hi); float S00 = lo + hi;
    upk(E4, lo, hi); float S10 = lo + hi;
    upk(C4, lo, hi); float S18 = lo + hi;
    upk(A4, lo, hi); float S1C = lo + hi;
    upk(B4, lo, hi); float S1E = lo + hi, S1F = lo - hi;

    float sg3 = ((__popc(t & 3) & 1) ? -1.0f : 1.0f);
    float sg6 = ((__popc(t & 6) & 1) ? -1.0f : 1.0f);
    float sg7 = ((__popc(t & 7) & 1) ? -1.0f : 1.0f);

    float r[8];
    r[0] = sg3 * S1F;   // Z0: mask 0x7F
    r[1] = sg6 * S00;   // Z1: mask 0xC0
    r[2] = sg7 * S00;   // Z2: mask 0xE0
    r[3] = sg7 * S10;   // 0xF0
    r[4] = sg7 * S18;   // 0xF8
    r[5] = sg7 * S1C;   // 0xFC
    r[6] = sg7 * S1E;   // 0xFE
    r[7] = sg7 * S1F;   // 0xFF

    // distributed transpose-reduction across the 8-lane group (7 shfls)
    int t0 = c_, t1 = b_, t2 = a_;
    float q4[4];
#pragma unroll
    for (int j = 0; j < 4; j++) {
        float keep = t0 ? r[2*j+1] : r[2*j];
        float send = t0 ? r[2*j]   : r[2*j+1];
        q4[j] = keep + __shfl_xor_sync(FULL, send, 1);
    }
    float q2[2];
#pragma unroll
    for (int j = 0; j < 2; j++) {
        float keep = t1 ? q4[2*j+1] : q4[2*j];
        float send = t1 ? q4[2*j]   : q4[2*j+1];
        q2[j] = keep + __shfl_xor_sync(FULL, send, 2);
    }
    float keep = t2 ? q2[1] : q2[0];
    float send = t2 ? q2[0] : q2[1];
    float res = keep + __shfl_xor_sync(FULL, send, 4);

    if (valid) out[b * 8 + t] = res;
}

extern "C" void kernel_launch(void* const* d_in, const int* in_sizes, int n_in,
                              void* d_out, int out_size)
{
    const float* x = (const float*)d_in[0];
    const float* w = (const float*)d_in[1];
    float* out = (float*)d_out;
    int B = in_sizes[0] / 8;

    qnn_setup<<<1, 32>>>(w);

    int warps = (B + 3) / 4;
    int blocks = (warps + 7) / 8;
    qnn_main<<<blocks, 256>>>(x, out, B);
}

// round 6
// speedup vs baseline: 1.9353x; 1.1806x over previous
#include <cuda_runtime.h>

#define DEVINL __device__ __forceinline__

typedef unsigned long long u64;

struct cplx { float x, y; };

DEVINL cplx cmul(cplx a, cplx b) {
    cplx r;
    r.x = fmaf(a.x, b.x, -a.y * b.y);
    r.y = fmaf(a.x, b.y,  a.y * b.x);
    return r;
}

// ---- packed f32x2 helpers ----
DEVINL u64 pk(float lo, float hi) {
    u64 r; asm("mov.b64 %0,{%1,%2};" : "=l"(r) : "f"(lo), "f"(hi)); return r;
}
DEVINL void upk(u64 a, float& lo, float& hi) {
    asm("mov.b64 {%0,%1},%2;" : "=f"(lo), "=f"(hi) : "l"(a));
}
DEVINL u64 spl(float v) { return pk(v, v); }
DEVINL u64 fma2(u64 a, u64 b, u64 c) {
    u64 r; asm("fma.rn.f32x2 %0,%1,%2,%3;" : "=l"(r) : "l"(a), "l"(b), "l"(c)); return r;
}
DEVINL u64 mul2(u64 a, u64 b) {
    u64 r; asm("mul.rn.f32x2 %0,%1,%2;" : "=l"(r) : "l"(a), "l"(b)); return r;
}
DEVINL u64 add2(u64 a, u64 b) {
    u64 r; asm("add.rn.f32x2 %0,%1,%2;" : "=l"(r) : "l"(a), "l"(b)); return r;
}
DEVINL u64 neg2(u64 a) { return a ^ 0x8000000080000000ULL; }
DEVINL u64 swp(u64 a) { float x, y; upk(a, x, y); return pk(y, x); }

// g_U[0][q]: full RZ*RY*RX (layer 0).
// g_U[1][q]: RY*RX only (layer-1 RZ drops out before |.|^2). SU(2).
// 8 floats: u00.x u00.y u01.x u01.y u10.x u10.y u11.x u11.y
__device__ float g_U[2][8][8];

__global__ void qnn_setup(const float* __restrict__ w) {
    int i = threadIdx.x;
    if (i >= 16) return;
    int l = i >> 3, q = i & 7;
    float a = w[(l * 8 + q) * 3 + 0];
    float b = w[(l * 8 + q) * 3 + 1];
    float c = w[(l * 8 + q) * 3 + 2];
    float sa, ca; sincosf(0.5f * a, &sa, &ca);
    float sb, cb; sincosf(0.5f * b, &sb, &cb);
    float sc, cc; sincosf(0.5f * c, &sc, &cc);
    cplx m00 = {  cb * ca,  sb * sa };
    cplx m01 = { -sb * ca, -cb * sa };
    cplx m10 = {  sb * ca, -cb * sa };
    cplx m11 = {  cb * ca, -sb * sa };
    cplx u00, u01, u10, u11;
    if (l == 0) {
        cplx e0 = { cc, -sc };
        cplx e1 = { cc,  sc };
        u00 = cmul(e0, m00); u01 = cmul(e0, m01);
        u10 = cmul(e1, m10); u11 = cmul(e1, m11);
    } else {
        u00 = m00; u01 = m01; u10 = m10; u11 = m11;   // RZ dropped
    }
    float* dst = g_U[l][q];
    dst[0] = u00.x; dst[1] = u00.y; dst[2] = u01.x; dst[3] = u01.y;
    dst[4] = u10.x; dst[5] = u10.y; dst[6] = u11.x; dst[7] = u11.y;
}

// Layout: 8 lanes per sample (g = lane>>3, t = lane&7).
// Full amp index bits [7..0] = [t2 t1 t0 | j4 j3 j2 j1 | j0], wire w <-> bit 7-w.
// Per lane: 16 packed (over j0) complex amps, k = (j4<<3)|(j3<<2)|(j2<<1)|j1.
__global__ void __launch_bounds__(256, 3) qnn_main(
    const float* __restrict__ x, float* __restrict__ out, int B)
{
    const unsigned FULL = 0xffffffffu;
    int L = threadIdx.x & 31;
    int warp = blockIdx.x * (blockDim.x >> 5) + (threadIdx.x >> 5);
    int g = L >> 3;
    int t = L & 7;
    int b = warp * 4 + g;
    bool valid = (b < B);

    float xv = valid ? x[b * 8 + t] : 0.0f;
    float s, c;
    __sincosf(0.5f * xv, &s, &c);

    // V_q = U[0][q]*RX(x_q) column 0 (embedding fused into layer-0).
    const float* u0 = g_U[0][t];
    cplx myv0, myv1;
    myv0.x = fmaf(c, u0[0],  s * u0[3]);
    myv0.y = fmaf(c, u0[1], -s * u0[2]);
    myv1.x = fmaf(c, u0[4],  s * u0[7]);
    myv1.y = fmaf(c, u0[5], -s * u0[6]);

    cplx va[8], vb[8];
    int base = L & ~7;
#pragma unroll
    for (int q = 0; q < 8; q++) {
        int src = base | q;
        va[q].x = __shfl_sync(FULL, myv0.x, src);
        va[q].y = __shfl_sync(FULL, myv0.y, src);
        vb[q].x = __shfl_sync(FULL, myv1.x, src);
        vb[q].y = __shfl_sync(FULL, myv1.y, src);
    }

    int a_ = (t >> 2) & 1, b_ = (t >> 1) & 1, c_ = t & 1;   // t2,t1,t0

    // ============================================================
    // Symbolic application of layer-1 gates on wires 0,1,2,3 to the
    // product state (CNOT ring re-associated as XOR args):
    // amp = v0[a'^j0] v1[a'^b'^j0] v2[b'^c'] v3[c'^d'] v4[d'^j3]
    //       * v5[j3^j2] v6[j2^j1] v7[j1^j0]
    // Result Q[j4][j3] packed over j0.
    // ============================================================
    const float* u0g = g_U[1][0];
    const float* u1g = g_U[1][1];
    const float* u2g = g_U[1][2];
    const float* u3g = g_U[1][3];
    cplx C0 = { u2g[4*c_ + 0], u2g[4*c_ + 1] };   // U2[c][0]
    cplx C1 = { u2g[4*c_ + 2], u2g[4*c_ + 3] };   // U2[c][1]
    cplx B0 = { u1g[4*b_ + 0], u1g[4*b_ + 1] };   // U1[b][0]
    cplx B1 = { u1g[4*b_ + 2], u1g[4*b_ + 3] };   // U1[b][1]
    cplx A0 = { u0g[4*a_ + 0], u0g[4*a_ + 1] };   // U0[a][0]
    cplx A1 = { u0g[4*a_ + 2], u0g[4*a_ + 3] };   // U0[a][1]

    // w[s][r] = U2[c][s] * v2[r^s]
    cplx w00 = cmul(C0, va[2]);
    cplx w01 = cmul(C0, vb[2]);
    cplx w10 = cmul(C1, vb[2]);
    cplx w11 = cmul(C1, va[2]);
    // z[r][e] = U1[b][r] * v1[e^r]
    cplx z00 = cmul(B0, va[1]);
    cplx z01 = cmul(B0, vb[1]);
    cplx z10 = cmul(B1, vb[1]);
    cplx z11 = cmul(B1, va[1]);

    // packed over j4': V3s0 = v3[j4'], V3s1 = v3[1^j4']
    u64 V30X = pk(va[3].x, vb[3].x), V30Y = pk(va[3].y, vb[3].y);
    u64 V31X = swp(V30X),            V31Y = swp(V30Y);

    // M[r](j4') = sum_s w[s][r] v3[s^j4']
    u64 MX[2], MY[2];
#pragma unroll
    for (int r = 0; r < 2; r++) {
        cplx s0 = r ? w01 : w00;
        cplx s1 = r ? w11 : w10;
        MX[r] = fma2(spl(s0.x), V30X, fma2(spl(-s0.y), V30Y,
                 fma2(spl(s1.x), V31X, mul2(spl(-s1.y), V31Y))));
        MY[r] = fma2(spl(s0.x), V30Y, fma2(spl(s0.y), V30X,
                 fma2(spl(s1.x), V31Y, mul2(spl(s1.y), V31X))));
    }

    // mj[r][j3](j4') = M[r](j4') * v4[j4'^j3]
    u64 V40X = pk(va[4].x, vb[4].x), V40Y = pk(va[4].y, vb[4].y);
    u64 V41X = swp(V40X),            V41Y = swp(V40Y);
    // g[r][j3](j4) = sum_{j4'} U3[j4,j4'] mj[r][j3](j4')
    u64 T0x = spl(u3g[0]);
    u64 T0y = pk(u3g[1], -u3g[1]);
    u64 nT0y = neg2(T0y);
    u64 T1x = pk(u3g[2], -u3g[2]);
    u64 T1y = spl(u3g[3]);
    u64 nT1y = neg2(T1y);
    u64 GX[2][2], GY[2][2];
#pragma unroll
    for (int r = 0; r < 2; r++) {
#pragma unroll
        for (int j3 = 0; j3 < 2; j3++) {
            u64 vx = j3 ? V41X : V40X, vy = j3 ? V41Y : V40Y;
            u64 mX = fma2(MX[r], vx, mul2(neg2(MY[r]), vy));
            u64 mY = fma2(MX[r], vy, mul2(MY[r], vx));
            u64 smX = swp(mX), smY = swp(mY);
            GX[r][j3] = fma2(T0x, mX, fma2(nT0y, mY, fma2(T1x, smX, mul2(nT1y, smY))));
            GY[r][j3] = fma2(T0x, mY, fma2(T0y, mX, fma2(T1x, smY, mul2(T1y, smX))));
        }
    }

    // N[e][j3] = sum_r z[r][e] (x) g[r][j3]
    u64 NX[2][2], NY[2][2];
#pragma unroll
    for (int e = 0; e < 2; e++) {
        cplx s0 = e ? z01 : z00;
        cplx s1 = e ? z11 : z10;
        u64 s0x = spl(s0.x), ns0y = spl(-s0.y), s0y = spl(s0.y);
        u64 s1x = spl(s1.x), ns1y = spl(-s1.y), s1y = spl(s1.y);
#pragma unroll
        for (int j3 = 0; j3 < 2; j3++) {
            NX[e][j3] = fma2(s0x, GX[0][j3], fma2(ns0y, GY[0][j3],
                         fma2(s1x, GX[1][j3], mul2(ns1y, GY[1][j3]))));
            NY[e][j3] = fma2(s0x, GY[0][j3], fma2(s0y, GX[0][j3],
                         fma2(s1x, GY[1][j3], mul2(s1y, GX[1][j3]))));
        }
    }
    // R[e][j3] = v0[e] (x) N[e][j3]
    u64 RXa[2][2], RYa[2][2];
#pragma unroll
    for (int e = 0; e < 2; e++) {
        cplx v = e ? vb[0] : va[0];
        u64 vx = spl(v.x), nvy = spl(-v.y), vy = spl(v.y);
#pragma unroll
        for (int j3 = 0; j3 < 2; j3++) {
            RXa[e][j3] = fma2(vx, NX[e][j3], mul2(nvy, NY[e][j3]));
            RYa[e][j3] = fma2(vx, NY[e][j3], mul2(vy, NX[e][j3]));
        }
    }
    // P[j0][j3] = A0 (x) R[j0][j3] + A1 (x) R[j0^1][j3]  (packed over j4)
    u64 PX[2][2], PY[2][2];
    {
        u64 a0x = spl(A0.x), na0y = spl(-A0.y), a0y = spl(A0.y);
        u64 a1x = spl(A1.x), na1y = spl(-A1.y), a1y = spl(A1.y);
#pragma unroll
        for (int j0 = 0; j0 < 2; j0++) {
#pragma unroll
            for (int j3 = 0; j3 < 2; j3++) {
                PX[j0][j3] = fma2(a0x, RXa[j0][j3], fma2(na0y, RYa[j0][j3],
                              fma2(a1x, RXa[j0^1][j3], mul2(na1y, RYa[j0^1][j3]))));
                PY[j0][j3] = fma2(a0x, RYa[j0][j3], fma2(a0y, RXa[j0][j3],
                              fma2(a1x, RYa[j0^1][j3], mul2(a1y, RXa[j0^1][j3]))));
            }
        }
    }
    // transpose to packed-over-j0: Q[j4][j3]
    u64 QX[2][2], QY[2][2];
#pragma unroll
    for (int j3 = 0; j3 < 2; j3++) {
        float p00, p01, p10, p11;
        upk(PX[0][j3], p00, p01); upk(PX[1][j3], p10, p11);
        QX[0][j3] = pk(p00, p10); QX[1][j3] = pk(p01, p11);
        upk(PY[0][j3], p00, p01); upk(PY[1][j3], p10, p11);
        QY[0][j3] = pk(p00, p10); QY[1][j3] = pk(p01, p11);
    }

    // ============================================================
    // Fold U5 (wire 5, bit j2) and U6 (wire 6, bit j1) into the chain
    // factors instead of sweeping them over the state:
    //   W67[j2'][j1](j0) = sum_{j1'} U6[j1,j1'] v6[j2'^j1'] v7[j1'^j0]
    //   CT[j3][j2][j1](j0) = sum_{j2'} U5[j2,j2'] v5[j3^j2'] W67[j2'][j1]
    //   amp[k] = Q[j4][j3] (.) CT[j3][j2][j1]
    // ============================================================
    u64 V7X[2], V7Y[2];
    V7X[0] = pk(va[7].x, vb[7].x); V7Y[0] = pk(va[7].y, vb[7].y);
    V7X[1] = swp(V7X[0]);          V7Y[1] = swp(V7Y[0]);

    const float* u6g = g_U[1][6];
    const float* u5g = g_U[1][5];
    u64 WX[2][2], WY[2][2];
#pragma unroll
    for (int j2p = 0; j2p < 2; j2p++) {
#pragma unroll
        for (int j1 = 0; j1 < 2; j1++) {
            cplx e0 = cmul((cplx){u6g[4*j1+0], u6g[4*j1+1]}, j2p ? vb[6] : va[6]);  // j1'=0
            cplx e1 = cmul((cplx){u6g[4*j1+2], u6g[4*j1+3]}, j2p ? va[6] : vb[6]);  // j1'=1
            WX[j2p][j1] = fma2(spl(e0.x), V7X[0], fma2(spl(-e0.y), V7Y[0],
                           fma2(spl(e1.x), V7X[1], mul2(spl(-e1.y), V7Y[1]))));
            WY[j2p][j1] = fma2(spl(e0.x), V7Y[0], fma2(spl(e0.y), V7X[0],
                           fma2(spl(e1.x), V7Y[1], mul2(spl(e1.y), V7X[1]))));
        }
    }

    u64 X[16], Y[16];
#pragma unroll
    for (int j3 = 0; j3 < 2; j3++) {
#pragma unroll
        for (int j2 = 0; j2 < 2; j2++) {
            cplx f0 = cmul((cplx){u5g[4*j2+0], u5g[4*j2+1]}, j3 ? vb[5] : va[5]);   // j2'=0
            cplx f1 = cmul((cplx){u5g[4*j2+2], u5g[4*j2+3]}, j3 ? va[5] : vb[5]);   // j2'=1
            u64 f0x = spl(f0.x), f0y = spl(f0.y), nf0y = spl(-f0.y);
            u64 f1x = spl(f1.x), f1y = spl(f1.y), nf1y = spl(-f1.y);
#pragma unroll
            for (int j1 = 0; j1 < 2; j1++) {
                u64 CTX = fma2(f0x, WX[0][j1], fma2(nf0y, WY[0][j1],
                            fma2(f1x, WX[1][j1], mul2(nf1y, WY[1][j1]))));
                u64 CTY = fma2(f0x, WY[0][j1], fma2(f0y, WX[0][j1],
                            fma2(f1x, WY[1][j1], mul2(f1y, WX[1][j1]))));
#pragma unroll
                for (int j4 = 0; j4 < 2; j4++) {
                    int k = (j4 << 3) | (j3 << 2) | (j2 << 1) | j1;
                    u64 nqy = neg2(QY[j4][j3]);
                    X[k] = fma2(QX[j4][j3], CTX, mul2(nqy, CTY));
                    Y[k] = fma2(QX[j4][j3], CTY, mul2(QY[j4][j3], CTX));
                }
            }
        }
    }

    // ---- remaining layer-1 gates: wire 4 local sweep, wire 7 packed ----
    {
        const float* u = g_U[1][4];
        u64 ax = spl(u[0]), ay = spl(u[1]), nay = spl(-u[1]);
        u64 bx = spl(u[2]), by = spl(u[3]), nby = spl(-u[3]);
        u64 nbx = spl(-u[2]);
        const int m = 4;   // bit j3
#pragma unroll
        for (int k = 0; k < 16; k++) {
            if ((k & m) == 0) {
                u64 X0 = X[k], Y0 = Y[k], X1 = X[k + m], Y1 = Y[k + m];
                X[k]     = fma2(ax, X0, fma2(nay, Y0, fma2(bx, X1, mul2(nby, Y1))));
                Y[k]     = fma2(ax, Y0, fma2(ay, X0, fma2(bx, Y1, mul2(by, X1))));
                X[k + m] = fma2(nbx, X0, fma2(nby, Y0, fma2(ax, X1, mul2(ay, Y1))));
                Y[k + m] = fma2(nbx, Y0, fma2(by, X0, fma2(ax, Y1, mul2(nay, X1))));
            }
        }
    }
    {   // wire 7 = packed dimension j0 (SU(2))
        const float* u = g_U[1][7];
        u64 CAx = spl(u[0]);
        u64 CAy = pk(u[1], -u[1]);
        u64 nCAy = neg2(CAy);
        u64 CBx = pk(u[2], -u[2]);
        u64 CBy = spl(u[3]);
        u64 nCBy = spl(-u[3]);
#pragma unroll
        for (int k = 0; k < 16; k++) {
            u64 X0 = X[k], Y0 = Y[k];
            u64 Xs = swp(X0), Ys = swp(Y0);
            X[k] = fma2(CAx, X0, fma2(nCAy, Y0, fma2(CBx, Xs, mul2(nCBy, Ys))));
            Y[k] = fma2(CAx, Y0, fma2(CAy, X0, fma2(CBx, Ys, mul2(CBy, Xs))));
        }
    }

    // ---- measurement: packed parity-sum tree (final ring folded in) ----
    u64 PR[16];
#pragma unroll
    for (int k = 0; k < 16; k++)
        PR[k] = fma2(X[k], X[k], mul2(Y[k], Y[k]));

    u64 m1 = spl(-1.0f);
    u64 SP[8], DP[8];
#pragma unroll
    for (int h = 0; h < 8; h++) {            // combine j1
        SP[h] = add2(PR[2*h], PR[2*h+1]);
        DP[h] = fma2(m1, PR[2*h+1], PR[2*h]);
    }
    u64 S2[4], A2[4], B2[4];
#pragma unroll
    for (int h = 0; h < 4; h++) {            // combine j2
        S2[h] = add2(SP[2*h], SP[2*h+1]);
        A2[h] = fma2(m1, SP[2*h+1], SP[2*h]);
        B2[h] = fma2(m1, DP[2*h+1], DP[2*h]);
    }
    u64 S3[2], C3[2], A3[2], B3[2];
#pragma unroll
    for (int h = 0; h < 2; h++) {            // combine j3
        S3[h] = add2(S2[2*h], S2[2*h+1]);
        C3[h] = fma2(m1, S2[2*h+1], S2[2*h]);
        A3[h] = fma2(m1, A2[2*h+1], A2[2*h]);
        B3[h] = fma2(m1, B2[2*h+1], B2[2*h]);
    }
    u64 S4 = add2(S3[0], S3[1]);             // combine j4
    u64 E4 = fma2(m1, S3[1], S3[0]);
    u64 C4 = fma2(m1, C3[1], C3[0]);
    u64 A4 = fma2(m1, A3[1], A3[0]);
    u64 B4 = fma2(m1, B3[1], B3[0]);

    float lo, hi;
    upk(S4, lo, hi); float S00 = lo + hi;
    upk(E4, lo, hi); float S10 = lo + hi;
    upk(C4, lo, hi); float S18 = lo + hi;
    upk(A4, lo, hi); float S1C = lo + hi;
    upk(B4, lo, hi); float S1E = lo + hi, S1F = lo - hi;

    float sg3 = ((__popc(t & 3) & 1) ? -1.0f : 1.0f);
    float sg6 = ((__popc(t & 6) & 1) ? -1.0f : 1.0f);
    float sg7 = ((__popc(t & 7) & 1) ? -1.0f : 1.0f);

    float r[8];
    r[0] = sg3 * S1F;   // Z0: mask 0x7F
    r[1] = sg6 * S00;   // Z1: mask 0xC0
    r[2] = sg7 * S00;   // Z2: mask 0xE0
    r[3] = sg7 * S10;   // 0xF0
    r[4] = sg7 * S18;   // 0xF8
    r[5] = sg7 * S1C;   // 0xFC
    r[6] = sg7 * S1E;   // 0xFE
    r[7] = sg7 * S1F;   // 0xFF

    // distributed transpose-reduction across the 8-lane group (7 shfls)
    int t0 = c_, t1 = b_, t2 = a_;
    float q4[4];
#pragma unroll
    for (int j = 0; j < 4; j++) {
        float keep = t0 ? r[2*j+1] : r[2*j];
        float send = t0 ? r[2*j]   : r[2*j+1];
        q4[j] = keep + __shfl_xor_sync(FULL, send, 1);
    }
    float q2[2];
#pragma unroll
    for (int j = 0; j < 2; j++) {
        float keep = t1 ? q4[2*j+1] : q4[2*j];
        float send = t1 ? q4[2*j]   : q4[2*j+1];
        q2[j] = keep + __shfl_xor_sync(FULL, send, 2);
    }
    float keep = t2 ? q2[1] : q2[0];
    float send = t2 ? q2[0] : q2[1];
    float res = keep + __shfl_xor_sync(FULL, send, 4);

    if (valid) out[b * 8 + t] = res;
}

extern "C" void kernel_launch(void* const* d_in, const int* in_sizes, int n_in,
                              void* d_out, int out_size)
{
    const float* x = (const float*)d_in[0];
    const float* w = (const float*)d_in[1];
    float* out = (float*)d_out;
    int B = in_sizes[0] / 8;

    qnn_setup<<<1, 32>>>(w);

    int warps = (B + 3) / 4;
    int blocks = (warps + 7) / 8;
    qnn_main<<<blocks, 256>>>(x, out, B);
}

// round 7
// speedup vs baseline: 2.0840x; 1.0768x over previous
#include <cuda_runtime.h>

#define DEVINL __device__ __forceinline__

typedef unsigned long long u64;

struct cplx { float x, y; };

DEVINL cplx cmul(cplx a, cplx b) {
    cplx r;
    r.x = fmaf(a.x, b.x, -a.y * b.y);
    r.y = fmaf(a.x, b.y,  a.y * b.x);
    return r;
}

// ---- packed f32x2 helpers ----
DEVINL u64 pk(float lo, float hi) {
    u64 r; asm("mov.b64 %0,{%1,%2};" : "=l"(r) : "f"(lo), "f"(hi)); return r;
}
DEVINL void upk(u64 a, float& lo, float& hi) {
    asm("mov.b64 {%0,%1},%2;" : "=f"(lo), "=f"(hi) : "l"(a));
}
DEVINL u64 spl(float v) { return pk(v, v); }
DEVINL u64 fma2(u64 a, u64 b, u64 c) {
    u64 r; asm("fma.rn.f32x2 %0,%1,%2,%3;" : "=l"(r) : "l"(a), "l"(b), "l"(c)); return r;
}
DEVINL u64 mul2(u64 a, u64 b) {
    u64 r; asm("mul.rn.f32x2 %0,%1,%2;" : "=l"(r) : "l"(a), "l"(b)); return r;
}
DEVINL u64 add2(u64 a, u64 b) {
    u64 r; asm("add.rn.f32x2 %0,%1,%2;" : "=l"(r) : "l"(a), "l"(b)); return r;
}
DEVINL u64 neg2(u64 a) { return a ^ 0x8000000080000000ULL; }
DEVINL u64 swp(u64 a) { float x, y; upk(a, x, y); return pk(y, x); }

// g_U[0][q]: full RZ*RY*RX (layer 0).
// g_U[1][q]: RY*RX only (layer-1 RZ drops out before |.|^2). SU(2).
// 8 floats: u00.x u00.y u01.x u01.y u10.x u10.y u11.x u11.y
__device__ float g_U[2][8][8];
// O3 = U[1][4]^dag Z U[1][4] = n.sigma : {nz, 2nx, 2ny, 0}
__device__ float g_O3[4];

__global__ void qnn_setup(const float* __restrict__ w) {
    int i = threadIdx.x;
    if (i >= 16) return;
    int l = i >> 3, q = i & 7;
    float a = w[(l * 8 + q) * 3 + 0];
    float b = w[(l * 8 + q) * 3 + 1];
    float c = w[(l * 8 + q) * 3 + 2];
    float sa, ca; sincosf(0.5f * a, &sa, &ca);
    float sb, cb; sincosf(0.5f * b, &sb, &cb);
    float sc, cc; sincosf(0.5f * c, &sc, &cc);
    cplx m00 = {  cb * ca,  sb * sa };
    cplx m01 = { -sb * ca, -cb * sa };
    cplx m10 = {  sb * ca, -cb * sa };
    cplx m11 = {  cb * ca, -sb * sa };
    cplx u00, u01, u10, u11;
    if (l == 0) {
        cplx e0 = { cc, -sc };
        cplx e1 = { cc,  sc };
        u00 = cmul(e0, m00); u01 = cmul(e0, m01);
        u10 = cmul(e1, m10); u11 = cmul(e1, m11);
    } else {
        u00 = m00; u01 = m01; u10 = m10; u11 = m11;   // RZ dropped
    }
    if (l == 1 && q == 4) {
        // O3 = M^dag Z M with M = RY*RX (RZ commutes with Z, drops out)
        float nz = (m00.x*m00.x + m00.y*m00.y) - (m10.x*m10.x + m10.y*m10.y);
        // c01 = conj(m00)*m01 - conj(m10)*m11 = nx - i*ny
        float cr = (m00.x*m01.x + m00.y*m01.y) - (m10.x*m11.x + m10.y*m11.y);
        float ci = (m00.x*m01.y - m00.y*m01.x) - (m10.x*m11.y - m10.y*m11.x);
        g_O3[0] = nz;
        g_O3[1] = 2.0f * cr;    // 2*nx
        g_O3[2] = -2.0f * ci;   // 2*ny
        g_O3[3] = 0.0f;
    }
    float* dst = g_U[l][q];
    dst[0] = u00.x; dst[1] = u00.y; dst[2] = u01.x; dst[3] = u01.y;
    dst[4] = u10.x; dst[5] = u10.y; dst[6] = u11.x; dst[7] = u11.y;
}

// Layout: 8 lanes per sample (g = lane>>3, t = lane&7).
// Full amp index bits [7..0] = [t2 t1 t0 | j4 j3 j2 j1 | j0], wire w <-> bit 7-w.
// Per lane: 16 packed (over j0) complex amps, k = (j4<<3)|(j3<<2)|(j2<<1)|j1.
__global__ void __launch_bounds__(256, 3) qnn_main(
    const float* __restrict__ x, float* __restrict__ out, int B)
{
    const unsigned FULL = 0xffffffffu;
    int L = threadIdx.x & 31;
    int warp = blockIdx.x * (blockDim.x >> 5) + (threadIdx.x >> 5);
    int g = L >> 3;
    int t = L & 7;
    int b = warp * 4 + g;
    bool valid = (b < B);

    float xv = valid ? x[b * 8 + t] : 0.0f;
    float s, c;
    __sincosf(0.5f * xv, &s, &c);

    // V_q = U[0][q]*RX(x_q) column 0 (embedding fused into layer-0).
    const float* u0 = g_U[0][t];
    cplx myv0, myv1;
    myv0.x = fmaf(c, u0[0],  s * u0[3]);
    myv0.y = fmaf(c, u0[1], -s * u0[2]);
    myv1.x = fmaf(c, u0[4],  s * u0[7]);
    myv1.y = fmaf(c, u0[5], -s * u0[6]);

    cplx va[8], vb[8];
    int base = L & ~7;
#pragma unroll
    for (int q = 0; q < 8; q++) {
        int src = base | q;
        va[q].x = __shfl_sync(FULL, myv0.x, src);
        va[q].y = __shfl_sync(FULL, myv0.y, src);
        vb[q].x = __shfl_sync(FULL, myv1.x, src);
        vb[q].y = __shfl_sync(FULL, myv1.y, src);
    }

    int a_ = (t >> 2) & 1, b_ = (t >> 1) & 1, c_ = t & 1;   // t2,t1,t0

    // ============================================================
    // Symbolic application of layer-1 gates on wires 0,1,2,3 to the
    // product state (CNOT ring re-associated as XOR args):
    // amp = v0[a'^j0] v1[a'^b'^j0] v2[b'^c'] v3[c'^d'] v4[d'^j3]
    //       * v5[j3^j2] v6[j2^j1] v7[j1^j0]
    // Result Q[j4][j3] packed over j0.
    // ============================================================
    const float* u0g = g_U[1][0];
    const float* u1g = g_U[1][1];
    const float* u2g = g_U[1][2];
    const float* u3g = g_U[1][3];
    cplx C0 = { u2g[4*c_ + 0], u2g[4*c_ + 1] };   // U2[c][0]
    cplx C1 = { u2g[4*c_ + 2], u2g[4*c_ + 3] };   // U2[c][1]
    cplx B0 = { u1g[4*b_ + 0], u1g[4*b_ + 1] };   // U1[b][0]
    cplx B1 = { u1g[4*b_ + 2], u1g[4*b_ + 3] };   // U1[b][1]
    cplx A0 = { u0g[4*a_ + 0], u0g[4*a_ + 1] };   // U0[a][0]
    cplx A1 = { u0g[4*a_ + 2], u0g[4*a_ + 3] };   // U0[a][1]

    // ---- packed cmul factories ----
    // w[s][r] = U2[c][s] * v2[r^s]: (w00,w01) = C0*(va2,vb2); (w10,w11) = C1*(vb2,va2)
    u64 V2X = pk(va[2].x, vb[2].x), V2Y = pk(va[2].y, vb[2].y);
    u64 V2Xs = swp(V2X), V2Ys = swp(V2Y);
    u64 WAX = fma2(spl(C0.x), V2X,  mul2(spl(-C0.y), V2Y));
    u64 WAY = fma2(spl(C0.x), V2Y,  mul2(spl(C0.y),  V2X));
    u64 WBX = fma2(spl(C1.x), V2Xs, mul2(spl(-C1.y), V2Ys));
    u64 WBY = fma2(spl(C1.x), V2Ys, mul2(spl(C1.y),  V2Xs));
    float w00x, w01x, w00y, w01y, w10x, w11x, w10y, w11y;
    upk(WAX, w00x, w01x); upk(WAY, w00y, w01y);
    upk(WBX, w10x, w11x); upk(WBY, w10y, w11y);

    // z[r][e] = U1[b][r] * v1[e^r]: (z00,z01) = B0*(va1,vb1); (z10,z11) = B1*(vb1,va1)
    u64 V1X = pk(va[1].x, vb[1].x), V1Y = pk(va[1].y, vb[1].y);
    u64 V1Xs = swp(V1X), V1Ys = swp(V1Y);
    u64 ZAX = fma2(spl(B0.x), V1X,  mul2(spl(-B0.y), V1Y));
    u64 ZAY = fma2(spl(B0.x), V1Y,  mul2(spl(B0.y),  V1X));
    u64 ZBX = fma2(spl(B1.x), V1Xs, mul2(spl(-B1.y), V1Ys));
    u64 ZBY = fma2(spl(B1.x), V1Ys, mul2(spl(B1.y),  V1Xs));
    float z00x, z01x, z00y, z01y, z10x, z11x, z10y, z11y;
    upk(ZAX, z00x, z01x); upk(ZAY, z00y, z01y);
    upk(ZBX, z10x, z11x); upk(ZBY, z10y, z11y);

    // packed over j4': V3s0 = v3[j4'], V3s1 = v3[1^j4']
    u64 V30X = pk(va[3].x, vb[3].x), V30Y = pk(va[3].y, vb[3].y);
    u64 V31X = swp(V30X),            V31Y = swp(V30Y);

    // M[r](j4') = sum_s w[s][r] v3[s^j4']
    u64 MX[2], MY[2];
#pragma unroll
    for (int r = 0; r < 2; r++) {
        float s0x = r ? w01x : w00x, s0y = r ? w01y : w00y;
        float s1x = r ? w11x : w10x, s1y = r ? w11y : w10y;
        MX[r] = fma2(spl(s0x), V30X, fma2(spl(-s0y), V30Y,
                 fma2(spl(s1x), V31X, mul2(spl(-s1y), V31Y))));
        MY[r] = fma2(spl(s0x), V30Y, fma2(spl(s0y), V30X,
                 fma2(spl(s1x), V31Y, mul2(spl(s1y), V31X))));
    }

    // mj[r][j3](j4') = M[r](j4') * v4[j4'^j3]
    u64 V40X = pk(va[4].x, vb[4].x), V40Y = pk(va[4].y, vb[4].y);
    u64 V41X = swp(V40X),            V41Y = swp(V40Y);
    // g[r][j3](j4) = sum_{j4'} U3[j4,j4'] mj[r][j3](j4')
    u64 T0x = spl(u3g[0]);
    u64 T0y = pk(u3g[1], -u3g[1]);
    u64 nT0y = neg2(T0y);
    u64 T1x = pk(u3g[2], -u3g[2]);
    u64 T1y = spl(u3g[3]);
    u64 nT1y = neg2(T1y);
    u64 GX[2][2], GY[2][2];
#pragma unroll
    for (int r = 0; r < 2; r++) {
#pragma unroll
        for (int j3 = 0; j3 < 2; j3++) {
            u64 vx = j3 ? V41X : V40X, vy = j3 ? V41Y : V40Y;
            u64 mX = fma2(MX[r], vx, mul2(neg2(MY[r]), vy));
            u64 mY = fma2(MX[r], vy, mul2(MY[r], vx));
            u64 smX = swp(mX), smY = swp(mY);
            GX[r][j3] = fma2(T0x, mX, fma2(nT0y, mY, fma2(T1x, smX, mul2(nT1y, smY))));
            GY[r][j3] = fma2(T0x, mY, fma2(T0y, mX, fma2(T1x, smY, mul2(T1y, smX))));
        }
    }

    // N[e][j3] = sum_r z[r][e] (x) g[r][j3]
    u64 NX[2][2], NY[2][2];
#pragma unroll
    for (int e = 0; e < 2; e++) {
        float s0xx = e ? z01x : z00x, s0yy = e ? z01y : z00y;
        float s1xx = e ? z11x : z10x, s1yy = e ? z11y : z10y;
        u64 s0x = spl(s0xx), ns0y = spl(-s0yy), s0y = spl(s0yy);
        u64 s1x = spl(s1xx), ns1y = spl(-s1yy), s1y = spl(s1yy);
#pragma unroll
        for (int j3 = 0; j3 < 2; j3++) {
            NX[e][j3] = fma2(s0x, GX[0][j3], fma2(ns0y, GY[0][j3],
                         fma2(s1x, GX[1][j3], mul2(ns1y, GY[1][j3]))));
            NY[e][j3] = fma2(s0x, GY[0][j3], fma2(s0y, GX[0][j3],
                         fma2(s1x, GY[1][j3], mul2(s1y, GX[1][j3]))));
        }
    }
    // R[e][j3] = v0[e] (x) N[e][j3]
    u64 RXa[2][2], RYa[2][2];
#pragma unroll
    for (int e = 0; e < 2; e++) {
        cplx v = e ? vb[0] : va[0];
        u64 vx = spl(v.x), nvy = spl(-v.y), vy = spl(v.y);
#pragma unroll
        for (int j3 = 0; j3 < 2; j3++) {
            RXa[e][j3] = fma2(vx, NX[e][j3], mul2(nvy, NY[e][j3]));
            RYa[e][j3] = fma2(vx, NY[e][j3], mul2(vy, NX[e][j3]));
        }
    }
    // P[j0][j3] = A0 (x) R[j0][j3] + A1 (x) R[j0^1][j3]  (packed over j4)
    u64 PX[2][2], PY[2][2];
    {
        u64 a0x = spl(A0.x), na0y = spl(-A0.y), a0y = spl(A0.y);
        u64 a1x = spl(A1.x), na1y = spl(-A1.y), a1y = spl(A1.y);
#pragma unroll
        for (int j0 = 0; j0 < 2; j0++) {
#pragma unroll
            for (int j3 = 0; j3 < 2; j3++) {
                PX[j0][j3] = fma2(a0x, RXa[j0][j3], fma2(na0y, RYa[j0][j3],
                              fma2(a1x, RXa[j0^1][j3], mul2(na1y, RYa[j0^1][j3]))));
                PY[j0][j3] = fma2(a0x, RYa[j0][j3], fma2(a0y, RXa[j0][j3],
                              fma2(a1x, RYa[j0^1][j3], mul2(a1y, RXa[j0^1][j3]))));
            }
        }
    }
    // transpose to packed-over-j0: Q[j4][j3]
    u64 QX[2][2], QY[2][2];
#pragma unroll
    for (int j3 = 0; j3 < 2; j3++) {
        float p00, p01, p10, p11;
        upk(PX[0][j3], p00, p01); upk(PX[1][j3], p10, p11);
        QX[0][j3] = pk(p00, p10); QX[1][j3] = pk(p01, p11);
        upk(PY[0][j3], p00, p01); upk(PY[1][j3], p10, p11);
        QY[0][j3] = pk(p00, p10); QY[1][j3] = pk(p01, p11);
    }

    // ============================================================
    // Fold U5 (bit j2) and U6 (bit j1) into the chain factors:
    //   W67[j2'][j1](j0) = sum_{j1'} U6[j1,j1'] v6[j2'^j1'] v7[j1'^j0]
    //   CT[j3][j2][j1](j0) = sum_{j2'} U5[j2,j2'] v5[j3^j2'] W67[j2'][j1]
    //   amp[k] = Q[j4][j3] (.) CT[j3][j2][j1]
    // ============================================================
    u64 V7X[2], V7Y[2];
    V7X[0] = pk(va[7].x, vb[7].x); V7Y[0] = pk(va[7].y, vb[7].y);
    V7X[1] = swp(V7X[0]);          V7Y[1] = swp(V7Y[0]);

    const float* u6g = g_U[1][6];
    const float* u5g = g_U[1][5];

    // packed e-factory: E0[j1] packed over j2' = U6[j1][0]*v6[j2'];
    //                   E1[j1] packed over j2' = U6[j1][1]*v6[1^j2']
    u64 V6X = pk(va[6].x, vb[6].x), V6Y = pk(va[6].y, vb[6].y);
    u64 V6Xs = swp(V6X), V6Ys = swp(V6Y);
    float e0x[2][2], e0y[2][2], e1x[2][2], e1y[2][2];   // [j1][j2']
#pragma unroll
    for (int j1 = 0; j1 < 2; j1++) {
        u64 E0X = fma2(spl(u6g[4*j1+0]), V6X,  mul2(spl(-u6g[4*j1+1]), V6Y));
        u64 E0Y = fma2(spl(u6g[4*j1+0]), V6Y,  mul2(spl(u6g[4*j1+1]),  V6X));
        u64 E1X = fma2(spl(u6g[4*j1+2]), V6Xs, mul2(spl(-u6g[4*j1+3]), V6Ys));
        u64 E1Y = fma2(spl(u6g[4*j1+2]), V6Ys, mul2(spl(u6g[4*j1+3]),  V6Xs));
        upk(E0X, e0x[j1][0], e0x[j1][1]); upk(E0Y, e0y[j1][0], e0y[j1][1]);
        upk(E1X, e1x[j1][0], e1x[j1][1]); upk(E1Y, e1y[j1][0], e1y[j1][1]);
    }

    u64 WX[2][2], WY[2][2];   // [j2'][j1]
#pragma unroll
    for (int j2p = 0; j2p < 2; j2p++) {
#pragma unroll
        for (int j1 = 0; j1 < 2; j1++) {
            u64 a0x = spl(e0x[j1][j2p]), a0y = spl(e0y[j1][j2p]);
            u64 a1x = spl(e1x[j1][j2p]), a1y = spl(e1y[j1][j2p]);
            WX[j2p][j1] = fma2(a0x, V7X[0], fma2(neg2(a0y), V7Y[0],
                           fma2(a1x, V7X[1], mul2(neg2(a1y), V7Y[1]))));
            WY[j2p][j1] = fma2(a0x, V7Y[0], fma2(a0y, V7X[0],
                           fma2(a1x, V7Y[1], mul2(a1y, V7X[1]))));
        }
    }

    // packed f-factory: F0[j2] packed over j3 = U5[j2][0]*v5[j3];
    //                   F1[j2] packed over j3 = U5[j2][1]*v5[1^j3]
    u64 V5X = pk(va[5].x, vb[5].x), V5Y = pk(va[5].y, vb[5].y);
    u64 V5Xs = swp(V5X), V5Ys = swp(V5Y);
    float f0x[2][2], f0y[2][2], f1x[2][2], f1y[2][2];   // [j2][j3]
#pragma unroll
    for (int j2 = 0; j2 < 2; j2++) {
        u64 F0X = fma2(spl(u5g[4*j2+0]), V5X,  mul2(spl(-u5g[4*j2+1]), V5Y));
        u64 F0Y = fma2(spl(u5g[4*j2+0]), V5Y,  mul2(spl(u5g[4*j2+1]),  V5X));
        u64 F1X = fma2(spl(u5g[4*j2+2]), V5Xs, mul2(spl(-u5g[4*j2+3]), V5Ys));
        u64 F1Y = fma2(spl(u5g[4*j2+2]), V5Ys, mul2(spl(u5g[4*j2+3]),  V5Xs));
        upk(F0X, f0x[j2][0], f0x[j2][1]); upk(F0Y, f0y[j2][0], f0y[j2][1]);
        upk(F1X, f1x[j2][0], f1x[j2][1]); upk(F1Y, f1y[j2][0], f1y[j2][1]);
    }

    u64 X[16], Y[16];
#pragma unroll
    for (int j3 = 0; j3 < 2; j3++) {
#pragma unroll
        for (int j2 = 0; j2 < 2; j2++) {
            u64 g0x = spl(f0x[j2][j3]), g0y = spl(f0y[j2][j3]), ng0y = neg2(g0y);
            u64 g1x = spl(f1x[j2][j3]), g1y = spl(f1y[j2][j3]), ng1y = neg2(g1y);
#pragma unroll
            for (int j1 = 0; j1 < 2; j1++) {
                u64 CTX = fma2(g0x, WX[0][j1], fma2(ng0y, WY[0][j1],
                            fma2(g1x, WX[1][j1], mul2(ng1y, WY[1][j1]))));
                u64 CTY = fma2(g0x, WY[0][j1], fma2(g0y, WX[0][j1],
                            fma2(g1x, WY[1][j1], mul2(g1y, WX[1][j1]))));
#pragma unroll
                for (int j4 = 0; j4 < 2; j4++) {
                    int k = (j4 << 3) | (j3 << 2) | (j2 << 1) | j1;
                    u64 nqy = neg2(QY[j4][j3]);
                    X[k] = fma2(QX[j4][j3], CTX, mul2(nqy, CTY));
                    Y[k] = fma2(QX[j4][j3], CTY, mul2(QY[j4][j3], CTX));
                }
            }
        }
    }

    // ---- wire 7 gate = packed dimension j0 (SU(2)); wire 4 folded into
    //      the measurement observable (Heisenberg), no sweep needed ----
    {
        const float* u = g_U[1][7];
        u64 CAx = spl(u[0]);
        u64 CAy = pk(u[1], -u[1]);
        u64 nCAy = neg2(CAy);
        u64 CBx = pk(u[2], -u[2]);
        u64 CBy = spl(u[3]);
        u64 nCBy = spl(-u[3]);
#pragma unroll
        for (int k = 0; k < 16; k++) {
            u64 X0 = X[k], Y0 = Y[k];
            u64 Xs = swp(X0), Ys = swp(Y0);
            X[k] = fma2(CAx, X0, fma2(nCAy, Y0, fma2(CBx, Xs, mul2(nCBy, Ys))));
            Y[k] = fma2(CAx, Y0, fma2(CAy, X0, fma2(CBx, Ys, mul2(CBy, Xs))));
        }
    }

    // ---- measurement: parity sums with O3 = n.sigma at bit j3 ----
    // For each (j4,j2,j1) pair over j3 (k0: j3=0, k1=k0|4):
    //   SP3 = |a0|^2+|a1|^2 ;  T = nz*(|a0|^2-|a1|^2) + 2nx*Re(a0* a1) + 2ny*Im(a0* a1)
    u64 nzp = spl(g_O3[0]);
    u64 nxp = spl(g_O3[1]);   // 2*nx
    u64 nyp = spl(g_O3[2]);   // 2*ny
    u64 m1 = spl(-1.0f);

    u64 SP3[8], T[8];
#pragma unroll
    for (int idx = 0; idx < 8; idx++) {
        int j4 = (idx >> 2) & 1, j2 = (idx >> 1) & 1, j1 = idx & 1;
        int k0 = (j4 << 3) | (j2 << 1) | j1;
        int k1 = k0 | 4;
        u64 PR0 = fma2(X[k0], X[k0], mul2(Y[k0], Y[k0]));
        u64 PR1 = fma2(X[k1], X[k1], mul2(Y[k1], Y[k1]));
        SP3[idx] = add2(PR0, PR1);
        u64 DP3 = fma2(m1, PR1, PR0);
        u64 CR = fma2(X[k0], X[k1], mul2(Y[k0], Y[k1]));              // Re(a0* a1)
        u64 CI = fma2(X[k0], Y[k1], mul2(neg2(Y[k0]), X[k1]));        // Im(a0* a1)
        T[idx] = fma2(nzp, DP3, fma2(nxp, CR, mul2(nyp, CI)));
    }

    // SP tree -> S00 (mask 0x00), S10 (mask 0x10: sign j4)
    u64 U0 = add2(SP3[0], SP3[1]), U1 = add2(SP3[2], SP3[3]);
    u64 U2 = add2(SP3[4], SP3[5]), U3v = add2(SP3[6], SP3[7]);
    u64 Vs0 = add2(U0, U1), Vs1 = add2(U2, U3v);
    u64 S00p = add2(Vs0, Vs1);
    u64 S10p = fma2(m1, Vs1, Vs0);

    // T tree -> S18 (j4), S1C (j4,j2), S1E (j4,j2,j1), S1F (+j0 via lo-hi)
    u64 Ts0 = add2(T[0], T[1]), Ts1 = add2(T[2], T[3]);
    u64 Ts2 = add2(T[4], T[5]), Ts3 = add2(T[6], T[7]);
    u64 Td0 = fma2(m1, T[1], T[0]), Td1 = fma2(m1, T[3], T[2]);
    u64 Td2 = fma2(m1, T[5], T[4]), Td3 = fma2(m1, T[7], T[6]);
    u64 Tss0 = add2(Ts0, Ts1), Tss1 = add2(Ts2, Ts3);
    u64 Tsd0 = fma2(m1, Ts1, Ts0), Tsd1 = fma2(m1, Ts3, Ts2);
    u64 Tdd0 = fma2(m1, Td1, Td0), Tdd1 = fma2(m1, Td3, Td2);
    u64 S18p = fma2(m1, Tss1, Tss0);
    u64 S1Cp = fma2(m1, Tsd1, Tsd0);
    u64 S1Ep = fma2(m1, Tdd1, Tdd0);

    float lo, hi;
    upk(S00p, lo, hi); float S00 = lo + hi;
    upk(S10p, lo, hi); float S10 = lo + hi;
    upk(S18p, lo, hi); float S18 = lo + hi;
    upk(S1Cp, lo, hi); float S1C = lo + hi;
    upk(S1Ep, lo, hi); float S1E = lo + hi, S1F = lo - hi;

    float sg3 = ((__popc(t & 3) & 1) ? -1.0f : 1.0f);
    float sg6 = ((__popc(t & 6) & 1) ? -1.0f : 1.0f);
    float sg7 = ((__popc(t & 7) & 1) ? -1.0f : 1.0f);

    float r[8];
    r[0] = sg3 * S1F;   // Z0: mask 0x7F
    r[1] = sg6 * S00;   // Z1: mask 0xC0
    r[2] = sg7 * S00;   // Z2: mask 0xE0
    r[3] = sg7 * S10;   // 0xF0
    r[4] = sg7 * S18;   // 0xF8
    r[5] = sg7 * S1C;   // 0xFC
    r[6] = sg7 * S1E;   // 0xFE
    r[7] = sg7 * S1F;   // 0xFF

    // distributed transpose-reduction across the 8-lane group (7 shfls)
    int t0 = c_, t1 = b_, t2 = a_;
    float q4[4];
#pragma unroll
    for (int j = 0; j < 4; j++) {
        float keep = t0 ? r[2*j+1] : r[2*j];
        float send = t0 ? r[2*j]   : r[2*j+1];
        q4[j] = keep + __shfl_xor_sync(FULL, send, 1);
    }
    float q2[2];
#pragma unroll
    for (int j = 0; j < 2; j++) {
        float keep = t1 ? q4[2*j+1] : q4[2*j];
        float send = t1 ? q4[2*j]   : q4[2*j+1];
        q2[j] = keep + __shfl_xor_sync(FULL, send, 2);
    }
    float keep = t2 ? q2[1] : q2[0];
    float send = t2 ? q2[0] : q2[1];
    float res = keep + __shfl_xor_sync(FULL, send, 4);

    if (valid) out[b * 8 + t] = res;
}

extern "C" void kernel_launch(void* const* d_in, const int* in_sizes, int n_in,
                              void* d_out, int out_size)
{
    const float* x = (const float*)d_in[0];
    const float* w = (const float*)d_in[1];
    float* out = (float*)d_out;
    int B = in_sizes[0] / 8;

    qnn_setup<<<1, 32>>>(w);

    int warps = (B + 3) / 4;
    int blocks = (warps + 7) / 8;
    qnn_main<<<blocks, 256>>>(x, out, B);
}

// round 8
// speedup vs baseline: 2.1498x; 1.0316x over previous
#include <cuda_runtime.h>

#define DEVINL __device__ __forceinline__

typedef unsigned long long u64;

struct cplx { float x, y; };

DEVINL cplx cmul(cplx a, cplx b) {
    cplx r;
    r.x = fmaf(a.x, b.x, -a.y * b.y);
    r.y = fmaf(a.x, b.y,  a.y * b.x);
    return r;
}

// ---- packed f32x2 helpers ----
DEVINL u64 pk(float lo, float hi) {
    u64 r; asm("mov.b64 %0,{%1,%2};" : "=l"(r) : "f"(lo), "f"(hi)); return r;
}
DEVINL void upk(u64 a, float& lo, float& hi) {
    asm("mov.b64 {%0,%1},%2;" : "=f"(lo), "=f"(hi) : "l"(a));
}
DEVINL u64 spl(float v) { return pk(v, v); }
DEVINL u64 fma2(u64 a, u64 b, u64 c) {
    u64 r; asm("fma.rn.f32x2 %0,%1,%2,%3;" : "=l"(r) : "l"(a), "l"(b), "l"(c)); return r;
}
DEVINL u64 mul2(u64 a, u64 b) {
    u64 r; asm("mul.rn.f32x2 %0,%1,%2;" : "=l"(r) : "l"(a), "l"(b)); return r;
}
DEVINL u64 add2(u64 a, u64 b) {
    u64 r; asm("add.rn.f32x2 %0,%1,%2;" : "=l"(r) : "l"(a), "l"(b)); return r;
}
DEVINL u64 neg2(u64 a) { return a ^ 0x8000000080000000ULL; }
DEVINL u64 swp(u64 a) { float x, y; upk(a, x, y); return pk(y, x); }

// g_U[0][q]: full RZ*RY*RX (layer 0).
// g_U[1][q]: RY*RX only (layer-1 RZ drops out before |.|^2). SU(2).
__device__ float g_U[2][8][8];
// Pre-packed gate constants (built in setup):
// [0..5]  U3:  T0x T0y nT0y T1x T1y nT1y
// [6..11] U7:  CAx CAy nCAy CBx CBy nCBy
// [12..14] O3: nzp nxp nyp (splatted)
__device__ u64 g_Cpk[16];

__global__ void qnn_setup(const float* __restrict__ w) {
    int i = threadIdx.x;
    if (i >= 16) return;
    int l = i >> 3, q = i & 7;
    float a = w[(l * 8 + q) * 3 + 0];
    float b = w[(l * 8 + q) * 3 + 1];
    float c = w[(l * 8 + q) * 3 + 2];
    float sa, ca; sincosf(0.5f * a, &sa, &ca);
    float sb, cb; sincosf(0.5f * b, &sb, &cb);
    float sc, cc; sincosf(0.5f * c, &sc, &cc);
    cplx m00 = {  cb * ca,  sb * sa };
    cplx m01 = { -sb * ca, -cb * sa };
    cplx m10 = {  sb * ca, -cb * sa };
    cplx m11 = {  cb * ca, -sb * sa };
    cplx u00, u01, u10, u11;
    if (l == 0) {
        cplx e0 = { cc, -sc };
        cplx e1 = { cc,  sc };
        u00 = cmul(e0, m00); u01 = cmul(e0, m01);
        u10 = cmul(e1, m10); u11 = cmul(e1, m11);
    } else {
        u00 = m00; u01 = m01; u10 = m10; u11 = m11;   // RZ dropped
    }
    if (l == 1 && q == 3) {
        // U3 packed constants (SU(2): alpha=m00, beta=m01)
        g_Cpk[0] = pk(m00.x,  m00.x);
        g_Cpk[1] = pk(m00.y, -m00.y);
        g_Cpk[2] = pk(-m00.y, m00.y);
        g_Cpk[3] = pk(m01.x, -m01.x);
        g_Cpk[4] = pk(m01.y,  m01.y);
        g_Cpk[5] = pk(-m01.y, -m01.y);
    }
    if (l == 1 && q == 7) {
        g_Cpk[6]  = pk(m00.x,  m00.x);
        g_Cpk[7]  = pk(m00.y, -m00.y);
        g_Cpk[8]  = pk(-m00.y, m00.y);
        g_Cpk[9]  = pk(m01.x, -m01.x);
        g_Cpk[10] = pk(m01.y,  m01.y);
        g_Cpk[11] = pk(-m01.y, -m01.y);
    }
    if (l == 1 && q == 4) {
        // O3 = M^dag Z M with M = RY*RX
        float nz = (m00.x*m00.x + m00.y*m00.y) - (m10.x*m10.x + m10.y*m10.y);
        float cr = (m00.x*m01.x + m00.y*m01.y) - (m10.x*m11.x + m10.y*m11.y);
        float ci = (m00.x*m01.y - m00.y*m01.x) - (m10.x*m11.y - m10.y*m11.x);
        g_Cpk[12] = pk(nz, nz);
        g_Cpk[13] = pk(2.0f * cr, 2.0f * cr);      // 2*nx
        g_Cpk[14] = pk(-2.0f * ci, -2.0f * ci);    // 2*ny
    }
    float* dst = g_U[l][q];
    dst[0] = u00.x; dst[1] = u00.y; dst[2] = u01.x; dst[3] = u01.y;
    dst[4] = u10.x; dst[5] = u10.y; dst[6] = u11.x; dst[7] = u11.y;
}

// Layout: 8 lanes per sample (g = lane>>3, t = lane&7).
// Full amp index bits [7..0] = [t2 t1 t0 | j4 j3 j2 j1 | j0], wire w <-> bit 7-w.
// Per lane: 16 packed (over j0) complex amps, k = (j4<<3)|(j3<<2)|(j2<<1)|j1.
__global__ void __launch_bounds__(256, 3) qnn_main(
    const float* __restrict__ x, float* __restrict__ out, int B)
{
    const unsigned FULL = 0xffffffffu;
    int L = threadIdx.x & 31;
    int warp = blockIdx.x * (blockDim.x >> 5) + (threadIdx.x >> 5);
    int g = L >> 3;
    int t = L & 7;
    int b = warp * 4 + g;
    bool valid = (b < B);

    float xv = valid ? x[b * 8 + t] : 0.0f;
    float s, c;
    __sincosf(0.5f * xv, &s, &c);

    // V_q = U[0][q]*RX(x_q) column 0 (embedding fused into layer-0).
    const float* u0 = g_U[0][t];
    cplx myv0, myv1;
    myv0.x = fmaf(c, u0[0],  s * u0[3]);
    myv0.y = fmaf(c, u0[1], -s * u0[2]);
    myv1.x = fmaf(c, u0[4],  s * u0[7]);
    myv1.y = fmaf(c, u0[5], -s * u0[6]);

    cplx va[8], vb[8];
    int base = L & ~7;
#pragma unroll
    for (int q = 0; q < 8; q++) {
        int src = base | q;
        va[q].x = __shfl_sync(FULL, myv0.x, src);
        va[q].y = __shfl_sync(FULL, myv0.y, src);
        vb[q].x = __shfl_sync(FULL, myv1.x, src);
        vb[q].y = __shfl_sync(FULL, myv1.y, src);
    }

    int a_ = (t >> 2) & 1, b_ = (t >> 1) & 1, c_ = t & 1;   // t2,t1,t0

    // ============================================================
    // Symbolic layer-1 gates on wires 0,1,2,3 against the product
    // state (CNOT ring as XOR args):
    // amp = v0[a'^j0] v1[a'^b'^j0] v2[b'^c'] v3[c'^d'] v4[d'^j3]
    //       * v5[j3^j2] v6[j2^j1] v7[j1^j0]
    // Result Q[j4][j3] packed over j0.
    // ============================================================
    const float* u0g = g_U[1][0];
    const float* u1g = g_U[1][1];
    const float* u2g = g_U[1][2];
    cplx C0 = { u2g[4*c_ + 0], u2g[4*c_ + 1] };   // U2[c][0]
    cplx C1 = { u2g[4*c_ + 2], u2g[4*c_ + 3] };   // U2[c][1]
    cplx B0 = { u1g[4*b_ + 0], u1g[4*b_ + 1] };   // U1[b][0]
    cplx B1 = { u1g[4*b_ + 2], u1g[4*b_ + 3] };   // U1[b][1]
    cplx A0 = { u0g[4*a_ + 0], u0g[4*a_ + 1] };   // U0[a][0]
    cplx A1 = { u0g[4*a_ + 2], u0g[4*a_ + 3] };   // U0[a][1]

    // ---- packed cmul factories ----
    // w[s][r] = U2[c][s]*v2[r^s]: (w00,w01)=C0*(va2,vb2); (w10,w11)=C1*(vb2,va2)
    u64 V2X = pk(va[2].x, vb[2].x), V2Y = pk(va[2].y, vb[2].y);
    u64 V2Xs = swp(V2X), V2Ys = swp(V2Y);
    u64 WAX = fma2(spl(C0.x), V2X,  mul2(spl(-C0.y), V2Y));
    u64 WAY = fma2(spl(C0.x), V2Y,  mul2(spl(C0.y),  V2X));
    u64 WBX = fma2(spl(C1.x), V2Xs, mul2(spl(-C1.y), V2Ys));
    u64 WBY = fma2(spl(C1.x), V2Ys, mul2(spl(C1.y),  V2Xs));
    float w00x, w01x, w00y, w01y, w10x, w11x, w10y, w11y;
    upk(WAX, w00x, w01x); upk(WAY, w00y, w01y);
    upk(WBX, w10x, w11x); upk(WBY, w10y, w11y);

    // z[r][e] = U1[b][r]*v1[e^r]: (z00,z01)=B0*(va1,vb1); (z10,z11)=B1*(vb1,va1)
    u64 V1X = pk(va[1].x, vb[1].x), V1Y = pk(va[1].y, vb[1].y);
    u64 V1Xs = swp(V1X), V1Ys = swp(V1Y);
    u64 ZAX = fma2(spl(B0.x), V1X,  mul2(spl(-B0.y), V1Y));
    u64 ZAY = fma2(spl(B0.x), V1Y,  mul2(spl(B0.y),  V1X));
    u64 ZBX = fma2(spl(B1.x), V1Xs, mul2(spl(-B1.y), V1Ys));
    u64 ZBY = fma2(spl(B1.x), V1Ys, mul2(spl(B1.y),  V1Xs));

    // zz[r][e] = v0[e]*z[r][e]  (packed over e)
    u64 V0X = pk(va[0].x, vb[0].x), V0Y = pk(va[0].y, vb[0].y);
    u64 ZZAX = fma2(ZAX, V0X, mul2(neg2(ZAY), V0Y));
    u64 ZZAY = fma2(ZAX, V0Y, mul2(ZAY, V0X));
    u64 ZZBX = fma2(ZBX, V0X, mul2(neg2(ZBY), V0Y));
    u64 ZZBY = fma2(ZBX, V0Y, mul2(ZBY, V0X));

    // ZP[r] packed over j0 = A0*zz[r][j0] + A1*zz[r][j0^1]
    u64 a0x = spl(A0.x), na0y = spl(-A0.y), a0y = spl(A0.y);
    u64 a1x = spl(A1.x), na1y = spl(-A1.y), a1y = spl(A1.y);
    u64 sZZAX = swp(ZZAX), sZZAY = swp(ZZAY);
    u64 sZZBX = swp(ZZBX), sZZBY = swp(ZZBY);
    u64 ZPAX = fma2(a0x, ZZAX, fma2(na0y, ZZAY, fma2(a1x, sZZAX, mul2(na1y, sZZAY))));
    u64 ZPAY = fma2(a0x, ZZAY, fma2(a0y, ZZAX, fma2(a1x, sZZAY, mul2(a1y, sZZAX))));
    u64 ZPBX = fma2(a0x, ZZBX, fma2(na0y, ZZBY, fma2(a1x, sZZBX, mul2(na1y, sZZBY))));
    u64 ZPBY = fma2(a0x, ZZBY, fma2(a0y, ZZBX, fma2(a1x, sZZBY, mul2(a1y, sZZBX))));
    float zp0x[2], zp0y[2], zp1x[2], zp1y[2];   // [j0]
    upk(ZPAX, zp0x[0], zp0x[1]); upk(ZPAY, zp0y[0], zp0y[1]);
    upk(ZPBX, zp1x[0], zp1x[1]); upk(ZPBY, zp1y[0], zp1y[1]);

    // packed over j4': V3s0 = v3[j4'], V3s1 = v3[1^j4']
    u64 V30X = pk(va[3].x, vb[3].x), V30Y = pk(va[3].y, vb[3].y);
    u64 V31X = swp(V30X),            V31Y = swp(V30Y);

    // M[r](j4') = sum_s w[s][r] v3[s^j4']
    u64 MX[2], MY[2];
#pragma unroll
    for (int r = 0; r < 2; r++) {
        float s0x = r ? w01x : w00x, s0y = r ? w01y : w00y;
        float s1x = r ? w11x : w10x, s1y = r ? w11y : w10y;
        MX[r] = fma2(spl(s0x), V30X, fma2(spl(-s0y), V30Y,
                 fma2(spl(s1x), V31X, mul2(spl(-s1y), V31Y))));
        MY[r] = fma2(spl(s0x), V30Y, fma2(spl(s0y), V30X,
                 fma2(spl(s1x), V31Y, mul2(spl(s1y), V31X))));
    }

    // mj[r][j3](j4') = M[r](j4') * v4[j4'^j3]
    u64 V40X = pk(va[4].x, vb[4].x), V40Y = pk(va[4].y, vb[4].y);
    u64 V41X = swp(V40X),            V41Y = swp(V40Y);
    // g[r][j3](j4) = sum_{j4'} U3[j4,j4'] mj[r][j3](j4')
    u64 T0x = g_Cpk[0], T0y = g_Cpk[1], nT0y = g_Cpk[2];
    u64 T1x = g_Cpk[3], T1y = g_Cpk[4], nT1y = g_Cpk[5];
    u64 nMY0 = neg2(MY[0]), nMY1 = neg2(MY[1]);
    u64 GX[2][2], GY[2][2];
#pragma unroll
    for (int r = 0; r < 2; r++) {
        u64 nMY = r ? nMY1 : nMY0;
#pragma unroll
        for (int j3 = 0; j3 < 2; j3++) {
            u64 vx = j3 ? V41X : V40X, vy = j3 ? V41Y : V40Y;
            u64 mX = fma2(MX[r], vx, mul2(nMY, vy));
            u64 mY = fma2(MX[r], vy, mul2(MY[r], vx));
            u64 smX = swp(mX), smY = swp(mY);
            GX[r][j3] = fma2(T0x, mX, fma2(nT0y, mY, fma2(T1x, smX, mul2(nT1y, smY))));
            GY[r][j3] = fma2(T0x, mY, fma2(T0y, mX, fma2(T1x, smY, mul2(T1y, smX))));
        }
    }

    // P[j0][j3] = sum_r ZP[r][j0] (x) G[r][j3]  (packed over j4)
    u64 PX[2][2], PY[2][2];
#pragma unroll
    for (int j0 = 0; j0 < 2; j0++) {
        u64 c0x = spl(zp0x[j0]), nc0y = spl(-zp0y[j0]), c0y = spl(zp0y[j0]);
        u64 c1x = spl(zp1x[j0]), nc1y = spl(-zp1y[j0]), c1y = spl(zp1y[j0]);
#pragma unroll
        for (int j3 = 0; j3 < 2; j3++) {
            PX[j0][j3] = fma2(c0x, GX[0][j3], fma2(nc0y, GY[0][j3],
                          fma2(c1x, GX[1][j3], mul2(nc1y, GY[1][j3]))));
            PY[j0][j3] = fma2(c0x, GY[0][j3], fma2(c0y, GX[0][j3],
                          fma2(c1x, GY[1][j3], mul2(c1y, GX[1][j3]))));
        }
    }
    // transpose to packed-over-j0: Q[j4][j3]
    u64 QX[2][2], QY[2][2];
#pragma unroll
    for (int j3 = 0; j3 < 2; j3++) {
        float p00, p01, p10, p11;
        upk(PX[0][j3], p00, p01); upk(PX[1][j3], p10, p11);
        QX[0][j3] = pk(p00, p10); QX[1][j3] = pk(p01, p11);
        upk(PY[0][j3], p00, p01); upk(PY[1][j3], p10, p11);
        QY[0][j3] = pk(p00, p10); QY[1][j3] = pk(p01, p11);
    }

    // U7 premix (fused sweep): QA = CA o Q ; QB = CB o swp(Q)
    u64 CAx = g_Cpk[6], CAy = g_Cpk[7], nCAy = g_Cpk[8];
    u64 CBx = g_Cpk[9], CBy = g_Cpk[10], nCBy = g_Cpk[11];
    u64 QAX[2][2], QAY[2][2], nQAY[2][2], QBX[2][2], QBY[2][2], nQBY[2][2];
#pragma unroll
    for (int j4 = 0; j4 < 2; j4++) {
#pragma unroll
        for (int j3 = 0; j3 < 2; j3++) {
            u64 qx = QX[j4][j3], qy = QY[j4][j3];
            u64 sqx = swp(qx), sqy = swp(qy);
            QAX[j4][j3] = fma2(CAx, qx, mul2(nCAy, qy));
            QAY[j4][j3] = fma2(CAx, qy, mul2(CAy, qx));
            QBX[j4][j3] = fma2(CBx, sqx, mul2(nCBy, sqy));
            QBY[j4][j3] = fma2(CBx, sqy, mul2(CBy, sqx));
            nQAY[j4][j3] = neg2(QAY[j4][j3]);
            nQBY[j4][j3] = neg2(QBY[j4][j3]);
        }
    }

    // ============================================================
    // Chain with U5/U6 folded:
    //   W67[j2'][j1](j0) = sum_{j1'} U6[j1,j1'] v6[j2'^j1'] v7[j1'^j0]
    //   CT[j3][j2][j1](j0) = sum_{j2'} U5[j2,j2'] v5[j3^j2'] W67[j2'][j1]
    //   amp[k] = QA (.) CT + QB (.) swp(CT)   (U7 fused)
    // ============================================================
    u64 V7X[2], V7Y[2];
    V7X[0] = pk(va[7].x, vb[7].x); V7Y[0] = pk(va[7].y, vb[7].y);
    V7X[1] = swp(V7X[0]);          V7Y[1] = swp(V7Y[0]);

    const float* u6g = g_U[1][6];
    const float* u5g = g_U[1][5];

    // e-factory: E0[j1] over j2' = U6[j1][0]*v6[j2']; E1[j1] over j2' = U6[j1][1]*v6[1^j2']
    u64 V6X = pk(va[6].x, vb[6].x), V6Y = pk(va[6].y, vb[6].y);
    u64 V6Xs = swp(V6X), V6Ys = swp(V6Y);
    float e0x[2][2], e0y[2][2], e1x[2][2], e1y[2][2];   // [j1][j2']
#pragma unroll
    for (int j1 = 0; j1 < 2; j1++) {
        u64 E0X = fma2(spl(u6g[4*j1+0]), V6X,  mul2(spl(-u6g[4*j1+1]), V6Y));
        u64 E0Y = fma2(spl(u6g[4*j1+0]), V6Y,  mul2(spl(u6g[4*j1+1]),  V6X));
        u64 E1X = fma2(spl(u6g[4*j1+2]), V6Xs, mul2(spl(-u6g[4*j1+3]), V6Ys));
        u64 E1Y = fma2(spl(u6g[4*j1+2]), V6Ys, mul2(spl(u6g[4*j1+3]),  V6Xs));
        upk(E0X, e0x[j1][0], e0x[j1][1]); upk(E0Y, e0y[j1][0], e0y[j1][1]);
        upk(E1X, e1x[j1][0], e1x[j1][1]); upk(E1Y, e1y[j1][0], e1y[j1][1]);
    }

    u64 WX[2][2], WY[2][2];   // [j2'][j1]
#pragma unroll
    for (int j2p = 0; j2p < 2; j2p++) {
#pragma unroll
        for (int j1 = 0; j1 < 2; j1++) {
            u64 b0x = spl(e0x[j1][j2p]), b0y = spl(e0y[j1][j2p]);
            u64 b1x = spl(e1x[j1][j2p]), b1y = spl(e1y[j1][j2p]);
            WX[j2p][j1] = fma2(b0x, V7X[0], fma2(neg2(b0y), V7Y[0],
                           fma2(b1x, V7X[1], mul2(neg2(b1y), V7Y[1]))));
            WY[j2p][j1] = fma2(b0x, V7Y[0], fma2(b0y, V7X[0],
                           fma2(b1x, V7Y[1], mul2(b1y, V7X[1]))));
        }
    }

    // f-factory: F0[j2] over j3 = U5[j2][0]*v5[j3]; F1[j2] over j3 = U5[j2][1]*v5[1^j3]
    u64 V5X = pk(va[5].x, vb[5].x), V5Y = pk(va[5].y, vb[5].y);
    u64 V5Xs = swp(V5X), V5Ys = swp(V5Y);
    float f0x[2][2], f0y[2][2], f1x[2][2], f1y[2][2];   // [j2][j3]
#pragma unroll
    for (int j2 = 0; j2 < 2; j2++) {
        u64 F0X = fma2(spl(u5g[4*j2+0]), V5X,  mul2(spl(-u5g[4*j2+1]), V5Y));
        u64 F0Y = fma2(spl(u5g[4*j2+0]), V5Y,  mul2(spl(u5g[4*j2+1]),  V5X));
        u64 F1X = fma2(spl(u5g[4*j2+2]), V5Xs, mul2(spl(-u5g[4*j2+3]), V5Ys));
        u64 F1Y = fma2(spl(u5g[4*j2+2]), V5Ys, mul2(spl(u5g[4*j2+3]),  V5Xs));
        upk(F0X, f0x[j2][0], f0x[j2][1]); upk(F0Y, f0y[j2][0], f0y[j2][1]);
        upk(F1X, f1x[j2][0], f1x[j2][1]); upk(F1Y, f1y[j2][0], f1y[j2][1]);
    }

    // assembly with fused U7
    u64 X[16], Y[16];
#pragma unroll
    for (int j3 = 0; j3 < 2; j3++) {
#pragma unroll
        for (int j2 = 0; j2 < 2; j2++) {
            u64 g0x = spl(f0x[j2][j3]), g0y = spl(f0y[j2][j3]), ng0y = neg2(g0y);
            u64 g1x = spl(f1x[j2][j3]), g1y = spl(f1y[j2][j3]), ng1y = neg2(g1y);
#pragma unroll
            for (int j1 = 0; j1 < 2; j1++) {
                u64 CTX = fma2(g0x, WX[0][j1], fma2(ng0y, WY[0][j1],
                            fma2(g1x, WX[1][j1], mul2(ng1y, WY[1][j1]))));
                u64 CTY = fma2(g0x, WY[0][j1], fma2(g0y, WX[0][j1],
                            fma2(g1x, WY[1][j1], mul2(g1y, WX[1][j1]))));
                u64 CTXs = swp(CTX), CTYs = swp(CTY);
#pragma unroll
                for (int j4 = 0; j4 < 2; j4++) {
                    int k = (j4 << 3) | (j3 << 2) | (j2 << 1) | j1;
                    X[k] = fma2(QAX[j4][j3], CTX, fma2(nQAY[j4][j3], CTY,
                             fma2(QBX[j4][j3], CTXs, mul2(nQBY[j4][j3], CTYs))));
                    Y[k] = fma2(QAX[j4][j3], CTY, fma2(QAY[j4][j3], CTX,
                             fma2(QBX[j4][j3], CTYs, mul2(QBY[j4][j3], CTXs))));
                }
            }
        }
    }

    // ---- measurement: parity sums with O3 = n.sigma at bit j3 ----
    u64 nzp = g_Cpk[12];
    u64 nxp = g_Cpk[13];
    u64 nyp = g_Cpk[14];
    u64 m1 = spl(-1.0f);

    u64 SP3[8], T[8];
#pragma unroll
    for (int idx = 0; idx < 8; idx++) {
        int j4 = (idx >> 2) & 1, j2 = (idx >> 1) & 1, j1 = idx & 1;
        int k0 = (j4 << 3) | (j2 << 1) | j1;
        int k1 = k0 | 4;
        u64 PR0 = fma2(X[k0], X[k0], mul2(Y[k0], Y[k0]));
        u64 PR1 = fma2(X[k1], X[k1], mul2(Y[k1], Y[k1]));
        SP3[idx] = add2(PR0, PR1);
        u64 DP3 = fma2(m1, PR1, PR0);
        u64 CR = fma2(X[k0], X[k1], mul2(Y[k0], Y[k1]));              // Re(a0* a1)
        u64 CI = fma2(X[k0], Y[k1], mul2(neg2(Y[k0]), X[k1]));        // Im(a0* a1)
        T[idx] = fma2(nzp, DP3, fma2(nxp, CR, mul2(nyp, CI)));
    }

    // SP tree -> S00 (mask 0x00), S10 (mask 0x10)
    u64 U0 = add2(SP3[0], SP3[1]), U1 = add2(SP3[2], SP3[3]);
    u64 U2 = add2(SP3[4], SP3[5]), U3v = add2(SP3[6], SP3[7]);
    u64 Vs0 = add2(U0, U1), Vs1 = add2(U2, U3v);
    u64 S00p = add2(Vs0, Vs1);
    u64 S10p = fma2(m1, Vs1, Vs0);

    // T tree -> S18, S1C, S1E, S1F
    u64 Ts0 = add2(T[0], T[1]), Ts1 = add2(T[2], T[3]);
    u64 Ts2 = add2(T[4], T[5]), Ts3 = add2(T[6], T[7]);
    u64 Td0 = fma2(m1, T[1], T[0]), Td1 = fma2(m1, T[3], T[2]);
    u64 Td2 = fma2(m1, T[5], T[4]), Td3 = fma2(m1, T[7], T[6]);
    u64 Tss0 = add2(Ts0, Ts1), Tss1 = add2(Ts2, Ts3);
    u64 Tsd0 = fma2(m1, Ts1, Ts0), Tsd1 = fma2(m1, Ts3, Ts2);
    u64 Tdd0 = fma2(m1, Td1, Td0), Tdd1 = fma2(m1, Td3, Td2);
    u64 S18p = fma2(m1, Tss1, Tss0);
    u64 S1Cp = fma2(m1, Tsd1, Tsd0);
    u64 S1Ep = fma2(m1, Tdd1, Tdd0);

    float lo, hi;
    upk(S00p, lo, hi); float S00 = lo + hi;
    upk(S10p, lo, hi); float S10 = lo + hi;
    upk(S18p, lo, hi); float S18 = lo + hi;
    upk(S1Cp, lo, hi); float S1C = lo + hi;
    upk(S1Ep, lo, hi); float S1E = lo + hi, S1F = lo - hi;

    float sg3 = ((__popc(t & 3) & 1) ? -1.0f : 1.0f);
    float sg6 = ((__popc(t & 6) & 1) ? -1.0f : 1.0f);
    float sg7 = ((__popc(t & 7) & 1) ? -1.0f : 1.0f);

    float r[8];
    r[0] = sg3 * S1F;   // Z0: mask 0x7F
    r[1] = sg6 * S00;   // Z1: mask 0xC0
    r[2] = sg7 * S00;   // Z2: mask 0xE0
    r[3] = sg7 * S10;   // 0xF0
    r[4] = sg7 * S18;   // 0xF8
    r[5] = sg7 * S1C;   // 0xFC
    r[6] = sg7 * S1E;   // 0xFE
    r[7] = sg7 * S1F;   // 0xFF

    // distributed transpose-reduction across the 8-lane group (7 shfls)
    int t0 = c_, t1 = b_, t2 = a_;
    float q4[4];
#pragma unroll
    for (int j = 0; j < 4; j++) {
        float keep = t0 ? r[2*j+1] : r[2*j];
        float send = t0 ? r[2*j]   : r[2*j+1];
        q4[j] = keep + __shfl_xor_sync(FULL, send, 1);
    }
    float q2[2];
#pragma unroll
    for (int j = 0; j < 2; j++) {
        float keep = t1 ? q4[2*j+1] : q4[2*j];
        float send = t1 ? q4[2*j]   : q4[2*j+1];
        q2[j] = keep + __shfl_xor_sync(FULL, send, 2);
    }
    float keep = t2 ? q2[1] : q2[0];
    float send = t2 ? q2[0] : q2[1];
    float res = keep + __shfl_xor_sync(FULL, send, 4);

    if (valid) out[b * 8 + t] = res;
}

extern "C" void kernel_launch(void* const* d_in, const int* in_sizes, int n_in,
                              void* d_out, int out_size)
{
    const float* x = (const float*)d_in[0];
    const float* w = (const float*)d_in[1];
    float* out = (float*)d_out;
    int B = in_sizes[0] / 8;

    qnn_setup<<<1, 32>>>(w);

    int warps = (B + 3) / 4;
    int blocks = (warps + 7) / 8;
    qnn_main<<<blocks, 256>>>(x, out, B);
}